// round 5
// baseline (speedup 1.0000x reference)
#include <cuda_runtime.h>
#include <cuda_bf16.h>
#include <cstdint>
#include <cstddef>
#include <math.h>

// Dims
#define Bn 32
#define Sn 128
#define Pn 32
#define In 512
#define Hn 512
#define G3 1536
#define On 10

// Output layout: out[32,10] | states[32,128,512] | context[32,512] | alpha[32,128]
#define OFF_OUT 0
#define OFF_ST  320
#define OFF_CTX 2097472
#define OFF_AL  2113856

// -------- scratch (__device__ globals; no allocations allowed) --------------
__device__ float g_conv[Sn*Bn*In];
__device__ float g_emb [Sn*Bn*In];
__device__ float g_gi0 [Sn*Bn*G3];
__device__ float g_st0 [Sn*Bn*Hn];
__device__ float g_gi1 [Sn*Bn*G3];
__device__ float g_hT  [Hn*Bn];        // h transposed: [k][b]
// tree barrier: 8 leaves on distinct 128B lines, 1 root, monotonic generation
__device__ __align__(128) unsigned g_leaf[8 * 32];   // leaf i at [i*32]
__device__ __align__(128) unsigned g_root;
__device__ __align__(128) unsigned g_bar_gen;

// -------- helpers -----------------------------------------------------------
__device__ __forceinline__ float wred(float v) {
    #pragma unroll
    for (int o = 16; o; o >>= 1) v += __shfl_xor_sync(0xffffffffu, v, o);
    return v;
}
__device__ __forceinline__ unsigned ld_acq(unsigned* p) {
    unsigned v;
    asm volatile("ld.acquire.gpu.u32 %0,[%1];" : "=r"(v) : "l"(p) : "memory");
    return v;
}
__device__ __forceinline__ unsigned atom_arrive_acqrel(unsigned* p) {
    unsigned o;
    asm volatile("atom.acq_rel.gpu.global.add.u32 %0,[%1],1;"
                 : "=r"(o) : "l"(p) : "memory");
    return o;
}
__device__ __forceinline__ void red_release_add(unsigned* p, unsigned v) {
    asm volatile("red.release.gpu.global.add.u32 [%0],%1;"
                 :: "l"(p), "r"(v) : "memory");
}
#define FMA2(d,a,b) asm("fma.rn.f32x2 %0,%1,%2,%0;" : "+l"(d) : "l"(a), "l"(b))
#define BCAST2(d,f) asm("mov.b64 %0,{%1,%1};" : "=l"(d) : "f"(f))
#define PACK2(d,x,y) asm("mov.b64 %0,{%1,%2};" : "=l"(d) : "f"(x), "f"(y))
#define UNPK2(x,y,d) asm("mov.b64 {%0,%1},%2;" : "=f"(x), "=f"(y) : "l"(d))

// ======== K1: conv-attention pooling over P (conv_b cancels in softmax) =====
__global__ __launch_bounds__(256)
void conv_pool_kernel(const float* __restrict__ in, const float* __restrict__ conv_w,
                      float* __restrict__ conv_all) {
    __shared__ float cw[In];
    __shared__ float sc[Pn];
    __shared__ float at[Pn];
    const int tid = threadIdx.x;
    const int bx = blockIdx.x;          // b*S + s
    const int b = bx >> 7, s = bx & 127;
    const float* base = in + (size_t)bx * (Pn * In);

    if (tid < 128) ((float4*)cw)[tid] = ((const float4*)conv_w)[tid];
    __syncthreads();

    const int w = tid >> 5, lane = tid & 31;
    #pragma unroll
    for (int q = 0; q < 4; q++) {
        int p = w * 4 + q;
        const float4* row = (const float4*)(base + (size_t)p * In);
        const float4* cw4 = (const float4*)cw;
        float acc = 0.f;
        for (int kk = lane; kk < 128; kk += 32) {
            float4 x = row[kk], y = cw4[kk];
            acc += x.x*y.x + x.y*y.y + x.z*y.z + x.w*y.w;
        }
        acc = wred(acc);
        if (lane == 0) sc[p] = acc;
    }
    __syncthreads();

    if (tid < 32) {
        float v = sc[tid], m = v;
        #pragma unroll
        for (int o = 16; o; o >>= 1) m = fmaxf(m, __shfl_xor_sync(0xffffffffu, m, o));
        float e = expf(v - m);
        float ssum = wred(e);
        at[tid] = e / ssum;
    }
    __syncthreads();

    float* dst = conv_all + ((size_t)s * Bn + b) * In;   // row = s*32+b
    for (int i = tid; i < In; i += 256) {
        float acc = 0.f;
        #pragma unroll 8
        for (int p = 0; p < Pn; p++) acc += at[p] * base[(size_t)p * In + i];
        dst[i] = acc;
    }
}

// ======== GEMM  C[M,N] = act(A[M,512] @ W[N,512]^T + bias) ==================
#define GBM 128
#define GBN 64
#define GBK 32
__global__ __launch_bounds__(256)
void gemm_tn(const float* __restrict__ A, const float* __restrict__ W,
             const float* __restrict__ bias, float* __restrict__ C,
             int N, int act) {
    __shared__ float As[GBK][GBM + 4];
    __shared__ float Ws[GBK][GBN + 4];
    const int tid = threadIdx.x;
    const int row0 = blockIdx.y * GBM;
    const int col0 = blockIdx.x * GBN;
    const int m0 = (tid >> 4) * 8;      // 0..120
    const int n0 = (tid & 15) * 4;      // 0..60
    unsigned long long acc[8][2];
    #pragma unroll
    for (int i = 0; i < 8; i++) { acc[i][0] = 0ULL; acc[i][1] = 0ULL; }

    for (int k0 = 0; k0 < 512; k0 += GBK) {
        #pragma unroll
        for (int l = 0; l < 4; l++) {
            int t = tid + l * 256;
            int m = t & 127, kq = t >> 7;   // kq 0..7
            float4 v = *(const float4*)(A + (size_t)(row0 + m) * 512 + k0 + kq * 4);
            As[kq*4+0][m] = v.x; As[kq*4+1][m] = v.y;
            As[kq*4+2][m] = v.z; As[kq*4+3][m] = v.w;
        }
        #pragma unroll
        for (int l = 0; l < 2; l++) {
            int t = tid + l * 256;
            int n = t & 63, kq = t >> 6;    // kq 0..7
            float4 v = *(const float4*)(W + (size_t)(col0 + n) * 512 + k0 + kq * 4);
            Ws[kq*4+0][n] = v.x; Ws[kq*4+1][n] = v.y;
            Ws[kq*4+2][n] = v.z; Ws[kq*4+3][n] = v.w;
        }
        __syncthreads();
        #pragma unroll
        for (int k = 0; k < GBK; k++) {
            float4 a0 = *(const float4*)&As[k][m0];
            float4 a1 = *(const float4*)&As[k][m0 + 4];
            float4 wv = *(const float4*)&Ws[k][n0];
            unsigned long long w01, w23;
            PACK2(w01, wv.x, wv.y);
            PACK2(w23, wv.z, wv.w);
            float am[8] = {a0.x,a0.y,a0.z,a0.w,a1.x,a1.y,a1.z,a1.w};
            #pragma unroll
            for (int i = 0; i < 8; i++) {
                unsigned long long ai;
                BCAST2(ai, am[i]);
                FMA2(acc[i][0], ai, w01);
                FMA2(acc[i][1], ai, w23);
            }
        }
        __syncthreads();
    }
    float bv0 = 0.f, bv1 = 0.f, bv2 = 0.f, bv3 = 0.f;
    if (bias) {
        bv0 = bias[col0+n0]; bv1 = bias[col0+n0+1];
        bv2 = bias[col0+n0+2]; bv3 = bias[col0+n0+3];
    }
    #pragma unroll
    for (int i = 0; i < 8; i++) {
        float c0, c1, c2, c3;
        UNPK2(c0, c1, acc[i][0]);
        UNPK2(c2, c3, acc[i][1]);
        float4 o = {c0 + bv0, c1 + bv1, c2 + bv2, c3 + bv3};
        if (act == 1) {
            o.x = fminf(1.f, fmaxf(-1.f, o.x));
            o.y = fminf(1.f, fmaxf(-1.f, o.y));
            o.z = fminf(1.f, fmaxf(-1.f, o.z));
            o.w = fminf(1.f, fmaxf(-1.f, o.w));
        }
        *(float4*)(C + (size_t)(row0 + m0 + i) * N + col0 + n0) = o;
    }
}

// ======== GRU persistent recurrence =========================================
// grid=128 CTAs (single wave), 256 thr. CTA c owns h-columns j in [4c,4c+4).
// Barrier: self-initializing tree (8 leaves x 16 arrivals -> root x 8 -> gen).
// smem: hs[512][32] (64KB) | wp[512][2][4] f32x2 pairs (32KB) | red (6KB) | bh
#define SM_HS   0
#define SM_WP   65536
#define SM_RED  (65536 + 32768)
#define SM_BH   (65536 + 32768 + 6144)
#define GRU_SMEM (65536 + 32768 + 6144 + 64)

__global__ __launch_bounds__(256)
void gru_kernel(const float* __restrict__ gi, const float* __restrict__ Whh,
                const float* __restrict__ bhh, float* __restrict__ st_out,
                int lay1) {
    extern __shared__ char sm[];
    float* hs = (float*)(sm + SM_HS);                      // [k*32 + b]
    unsigned long long* wp = (unsigned long long*)(sm + SM_WP);  // [k*8 + jp*4 + g]
    float2* red = (float2*)(sm + SM_RED);                  // [((ks*32+b)*2+jp)*3 + g]
    float* bh = (float*)(sm + SM_BH);                      // [12]
    const int tid = threadIdx.x;
    const int cta = blockIdx.x;

    // generation base: stable between kernels (previous grid fully finished)
    unsigned gen_base = 0;
    if (tid == 0) gen_base = *(volatile unsigned*)&g_bar_gen;

    // Pack W_hh slice once: pair rows (j, j+1) within gate g, pair index jp.
    #pragma unroll
    for (int r = 0; r < 12; r++) {
        int g = r >> 2, jl = r & 3, jp = jl >> 1, sel = jl & 1;
        int rowg = g * 512 + cta * 4 + jl;
        for (int k = tid; k < 512; k += 256)
            ((float*)&wp[(size_t)k * 8 + jp * 4 + g])[sel] = Whh[(size_t)rowg * 512 + k];
    }
    if (tid < 12) {
        int g = tid >> 2, jl = tid & 3;
        bh[tid] = bhh[g * 512 + cta * 4 + jl];
    }
    __syncthreads();

    const int b = tid & 31, jp = (tid >> 5) & 1, ks = tid >> 6;   // ks uniform per warp-pair
    const int kbeg = ks * 128;
    // gate-phase identity (tid < 128)
    const int bb = tid & 31, jl = (tid >> 5) & 3;
    const int jg = cta * 4 + jl;

    // prefetch gi for step 0
    float giv0 = 0.f, giv1 = 0.f, giv2 = 0.f;
    if (tid < 128) {
        giv0 = __ldg(gi + (size_t)bb * G3 + jg);
        giv1 = __ldg(gi + (size_t)bb * G3 + 512 + jg);
        giv2 = __ldg(gi + (size_t)bb * G3 + 1024 + jg);
    }

    for (int s = 0; s < 128; s++) {
        if (s > 0) {
            // ---- stage this pair's h chunk (16KB), then pair barrier ----
            {
                const int t64 = tid & 63;
                #pragma unroll
                for (int l = 0; l < 16; l++) {
                    int idx = ks * 1024 + t64 + l * 64;
                    ((float4*)hs)[idx] = ((const float4*)g_hT)[idx];
                }
            }
            asm volatile("bar.sync %0, 64;" :: "r"(1 + ks));

            // ---- partial dots: thread (b, jp, ks) -> 3 gate f32x2 accs ----
            unsigned long long a0 = 0ULL, a1 = 0ULL, a2 = 0ULL;
            const unsigned long long* wb = wp + jp * 4;
            #pragma unroll 4
            for (int kk = 0; kk < 128; kk++) {
                int k = kbeg + kk;
                float hk = hs[k * 32 + b];
                unsigned long long h2;
                BCAST2(h2, hk);
                ulonglong2 w01 = *(const ulonglong2*)(wb + (size_t)k * 8);
                unsigned long long w2v = wb[(size_t)k * 8 + 2];
                FMA2(a0, h2, w01.x);
                FMA2(a1, h2, w01.y);
                FMA2(a2, h2, w2v);
            }
            unsigned long long* rr = (unsigned long long*)&red[((ks * 32 + b) * 2 + jp) * 3];
            rr[0] = a0; rr[1] = a1; rr[2] = a2;
        }
        __syncthreads();

        // ---- gate math for the CTA's 4 columns ----
        if (tid < 128) {
            float gh0 = 0.f, gh1 = 0.f, gh2 = 0.f, ho = 0.f;
            if (s > 0) {
                int jpp = jl >> 1, sel = jl & 1;
                #pragma unroll
                for (int kk = 0; kk < 4; kk++) {
                    float2* q = &red[((kk * 32 + bb) * 2 + jpp) * 3];
                    float2 q0 = q[0], q1 = q[1], q2 = q[2];
                    gh0 += sel ? q0.y : q0.x;
                    gh1 += sel ? q1.y : q1.x;
                    gh2 += sel ? q2.y : q2.x;
                }
                ho = hs[jg * 32 + bb];
            }
            float r = 1.f / (1.f + expf(-(giv0 + gh0 + bh[jl])));
            float z = 1.f / (1.f + expf(-(giv1 + gh1 + bh[4 + jl])));
            float nn = tanhf(giv2 + r * (gh2 + bh[8 + jl]));
            float hn = (1.f - z) * nn + z * ho;
            g_hT[jg * 32 + bb] = hn;
            size_t oidx = lay1 ? ((size_t)bb * 128 + s) * 512 + jg
                               : ((size_t)s * 32 + bb) * 512 + jg;
            st_out[oidx] = hn;
        }
        __syncthreads();

        // ---- grid-wide tree barrier (8 leaves -> root -> gen) ----
        if (tid == 0) {
            unsigned old = atom_arrive_acqrel(&g_leaf[(cta & 7) * 32]);
            if (old == 15) {
                g_leaf[(cta & 7) * 32] = 0;          // published by root acq_rel atom
                unsigned r = atom_arrive_acqrel(&g_root);
                if (r == 7) {
                    g_root = 0;                       // published by gen release
                    red_release_add(&g_bar_gen, 1);
                }
            }
        }
        // prefetch next step's gi while tid0 polls (LDG in flight over the wait)
        if (s < 127 && tid < 128) {
            size_t gib = ((size_t)(s + 1) * 32 + bb) * (size_t)G3;
            giv0 = __ldg(gi + gib + jg);
            giv1 = __ldg(gi + gib + 512 + jg);
            giv2 = __ldg(gi + gib + 1024 + jg);
        }
        if (tid == 0) {
            unsigned target = gen_base + (unsigned)s + 1;
            while (ld_acq(&g_bar_gen) < target) { }
        }
        __syncthreads();
    }
}

// ======== final: time-attention + linear + softmax ==========================
// states layout here: [b][s][h] (written directly by layer-1 GRU into d_out)
__global__ __launch_bounds__(256)
void final_kernel(const float* __restrict__ states, const float* __restrict__ attw,
                  const float* __restrict__ demoip, const float* __restrict__ linW,
                  const float* __restrict__ linb, float* __restrict__ out) {
    __shared__ float aw[512];
    __shared__ float lg[128];
    __shared__ float al[128];
    __shared__ float ctx[512];
    __shared__ float o10[10];
    const int tid = threadIdx.x, b = blockIdx.x;
    const int w = tid >> 5, lane = tid & 31;
    const float* stb = states + (size_t)b * 128 * 512;

    for (int h = tid; h < 512; h += 256) aw[h] = attw[h];
    __syncthreads();

    for (int s = w; s < 128; s += 8) {
        const float* row = stb + (size_t)s * 512;
        float acc = 0.f;
        for (int h = lane; h < 512; h += 32) acc += row[h] * aw[h];
        acc = wred(acc);
        if (lane == 0) lg[s] = acc;
    }
    __syncthreads();

    if (tid < 32) {
        float v[4]; float m = -1e30f;
        #pragma unroll
        for (int q = 0; q < 4; q++) { v[q] = lg[tid + q * 32]; m = fmaxf(m, v[q]); }
        #pragma unroll
        for (int o = 16; o; o >>= 1) m = fmaxf(m, __shfl_xor_sync(0xffffffffu, m, o));
        float ssum = 0.f;
        #pragma unroll
        for (int q = 0; q < 4; q++) { v[q] = expf(v[q] - m); ssum += v[q]; }
        ssum = wred(ssum);
        #pragma unroll
        for (int q = 0; q < 4; q++) {
            float a = v[q] / ssum;
            al[tid + q * 32] = a;
            out[OFF_AL + b * 128 + tid + q * 32] = a;
        }
    }
    __syncthreads();

    for (int h = tid; h < 512; h += 256) {
        float acc = 0.f;
        for (int s = 0; s < 128; s++) acc += al[s] * stb[(size_t)s * 512 + h];
        ctx[h] = acc;
        out[OFF_CTX + b * 512 + h] = acc;
    }
    __syncthreads();

    if (tid < 10) {
        float acc = linb[tid];
        const float* wrow = linW + tid * 515;
        for (int h = 0; h < 512; h++) acc += ctx[h] * wrow[h];
        for (int d = 0; d < 3; d++) acc += demoip[b * 3 + d] * wrow[512 + d];
        o10[tid] = acc;
    }
    __syncthreads();
    if (tid < 10) {
        float m = -1e30f;
        for (int o = 0; o < 10; o++) m = fmaxf(m, o10[o]);
        float e = expf(o10[tid] - m), ssum = 0.f;
        for (int o = 0; o < 10; o++) ssum += expf(o10[o] - m);
        out[OFF_OUT + b * 10 + tid] = e / ssum;
    }
}

// ======== launch ============================================================
extern "C" void kernel_launch(void* const* d_in, const int* in_sizes, int n_in,
                              void* d_out, int out_size) {
    // batch_size may or may not be materialized as input[2] (size-1 scalar).
    int sh = (in_sizes[2] == 1) ? 1 : 0;

    const float* inp   = (const float*)d_in[0];
    const float* demo  = (const float*)d_in[1];
    const float* convw = (const float*)d_in[2 + sh];
    // conv_b at [3+sh] cancels in the softmax; unused.
    const float* embW  = (const float*)d_in[4 + sh];
    const float* Wi0   = (const float*)d_in[5 + sh];
    const float* Wh0   = (const float*)d_in[6 + sh];
    const float* bi0   = (const float*)d_in[7 + sh];
    const float* bh0   = (const float*)d_in[8 + sh];
    const float* Wi1   = (const float*)d_in[9 + sh];
    const float* Wh1   = (const float*)d_in[10 + sh];
    const float* bi1   = (const float*)d_in[11 + sh];
    const float* bh1   = (const float*)d_in[12 + sh];
    const float* attw  = (const float*)d_in[13 + sh];
    const float* linW  = (const float*)d_in[14 + sh];
    const float* linb  = (const float*)d_in[15 + sh];
    float* out = (float*)d_out;

    cudaFuncSetAttribute(gru_kernel, cudaFuncAttributeMaxDynamicSharedMemorySize, GRU_SMEM);

    void *pc, *pe, *p0, *ps0, *p1;
    cudaGetSymbolAddress(&pc, g_conv);
    cudaGetSymbolAddress(&pe, g_emb);
    cudaGetSymbolAddress(&p0, g_gi0);
    cudaGetSymbolAddress(&ps0, g_st0);
    cudaGetSymbolAddress(&p1, g_gi1);

    conv_pool_kernel<<<Bn * Sn, 256>>>(inp, convw, (float*)pc);

    dim3 ge(In / GBN, (Sn * Bn) / GBM);   // (8, 32)
    dim3 gg(G3 / GBN, (Sn * Bn) / GBM);   // (24, 32)
    gemm_tn<<<ge, 256>>>((const float*)pc, embW, nullptr, (float*)pe, In, 1);
    gemm_tn<<<gg, 256>>>((const float*)pe, Wi0, bi0, (float*)p0, G3, 0);

    gru_kernel<<<128, 256, GRU_SMEM>>>((const float*)p0, Wh0, bh0, (float*)ps0, 0);

    gemm_tn<<<gg, 256>>>((const float*)ps0, Wi1, bi1, (float*)p1, G3, 0);

    gru_kernel<<<128, 256, GRU_SMEM>>>((const float*)p1, Wh1, bh1, out + OFF_ST, 1);

    final_kernel<<<Bn, 256>>>(out + OFF_ST, attw, demo, linW, linb, out);
}

// round 6
// speedup vs baseline: 1.3109x; 1.3109x over previous
#include <cuda_runtime.h>
#include <cuda_bf16.h>
#include <cstdint>
#include <cstddef>
#include <math.h>

// Dims
#define Bn 32
#define Sn 128
#define Pn 32
#define In 512
#define Hn 512
#define G3 1536
#define On 10

// Output layout: out[32,10] | states[32,128,512] | context[32,512] | alpha[32,128]
#define OFF_OUT 0
#define OFF_ST  320
#define OFF_CTX 2097472
#define OFF_AL  2113856

// -------- scratch (__device__ globals; no allocations allowed) --------------
__device__ float g_conv[Sn*Bn*In];
__device__ float g_emb [Sn*Bn*In];
__device__ float g_gi0 [Sn*Bn*G3];
__device__ float g_st0 [Sn*Bn*Hn];
__device__ float g_gi1 [Sn*Bn*G3];
__device__ float g_hT2[2*Hn*Bn];     // double-buffered h, transposed [k][b]
// per-group progress counters: group q (CTAs 32q..32q+31) at [q*32], separate lines.
// Two arrays, one per GRU layer; each layer resets the OTHER layer's array.
__device__ __align__(128) unsigned g_grpA[4*32];
__device__ __align__(128) unsigned g_grpB[4*32];

// -------- helpers -----------------------------------------------------------
__device__ __forceinline__ float wred(float v) {
    #pragma unroll
    for (int o = 16; o; o >>= 1) v += __shfl_xor_sync(0xffffffffu, v, o);
    return v;
}
__device__ __forceinline__ unsigned ld_acq(unsigned* p) {
    unsigned v;
    asm volatile("ld.acquire.gpu.u32 %0,[%1];" : "=r"(v) : "l"(p) : "memory");
    return v;
}
__device__ __forceinline__ void red_release_add(unsigned* p, unsigned v) {
    asm volatile("red.release.gpu.global.add.u32 [%0],%1;"
                 :: "l"(p), "r"(v) : "memory");
}
#define FMA2(d,a,b) asm("fma.rn.f32x2 %0,%1,%2,%0;" : "+l"(d) : "l"(a), "l"(b))
#define BCAST2(d,f) asm("mov.b64 %0,{%1,%1};" : "=l"(d) : "f"(f))
#define PACK2(d,x,y) asm("mov.b64 %0,{%1,%2};" : "=l"(d) : "f"(x), "f"(y))
#define UNPK2(x,y,d) asm("mov.b64 {%0,%1},%2;" : "=f"(x), "=f"(y) : "l"(d))

// ======== K1: conv-attention pooling over P (conv_b cancels in softmax) =====
__global__ __launch_bounds__(256)
void conv_pool_kernel(const float* __restrict__ in, const float* __restrict__ conv_w,
                      float* __restrict__ conv_all) {
    __shared__ float cw[In];
    __shared__ float sc[Pn];
    __shared__ float at[Pn];
    const int tid = threadIdx.x;
    const int bx = blockIdx.x;          // b*S + s
    const int b = bx >> 7, s = bx & 127;
    const float* base = in + (size_t)bx * (Pn * In);

    if (tid < 128) ((float4*)cw)[tid] = ((const float4*)conv_w)[tid];
    __syncthreads();

    const int w = tid >> 5, lane = tid & 31;
    #pragma unroll
    for (int q = 0; q < 4; q++) {
        int p = w * 4 + q;
        const float4* row = (const float4*)(base + (size_t)p * In);
        const float4* cw4 = (const float4*)cw;
        float acc = 0.f;
        for (int kk = lane; kk < 128; kk += 32) {
            float4 x = row[kk], y = cw4[kk];
            acc += x.x*y.x + x.y*y.y + x.z*y.z + x.w*y.w;
        }
        acc = wred(acc);
        if (lane == 0) sc[p] = acc;
    }
    __syncthreads();

    if (tid < 32) {
        float v = sc[tid], m = v;
        #pragma unroll
        for (int o = 16; o; o >>= 1) m = fmaxf(m, __shfl_xor_sync(0xffffffffu, m, o));
        float e = expf(v - m);
        float ssum = wred(e);
        at[tid] = e / ssum;
    }
    __syncthreads();

    float* dst = conv_all + ((size_t)s * Bn + b) * In;   // row = s*32+b
    for (int i = tid; i < In; i += 256) {
        float acc = 0.f;
        #pragma unroll 8
        for (int p = 0; p < Pn; p++) acc += at[p] * base[(size_t)p * In + i];
        dst[i] = acc;
    }
}

// ======== GEMM  C[M,N] = act(A[M,512] @ W[N,512]^T + bias) ==================
#define GBM 128
#define GBN 64
#define GBK 32
__global__ __launch_bounds__(256)
void gemm_tn(const float* __restrict__ A, const float* __restrict__ W,
             const float* __restrict__ bias, float* __restrict__ C,
             int N, int act) {
    __shared__ float As[GBK][GBM + 4];
    __shared__ float Ws[GBK][GBN + 4];
    const int tid = threadIdx.x;
    const int row0 = blockIdx.y * GBM;
    const int col0 = blockIdx.x * GBN;
    const int m0 = (tid >> 4) * 8;      // 0..120
    const int n0 = (tid & 15) * 4;      // 0..60
    unsigned long long acc[8][2];
    #pragma unroll
    for (int i = 0; i < 8; i++) { acc[i][0] = 0ULL; acc[i][1] = 0ULL; }

    for (int k0 = 0; k0 < 512; k0 += GBK) {
        #pragma unroll
        for (int l = 0; l < 4; l++) {
            int t = tid + l * 256;
            int m = t & 127, kq = t >> 7;   // kq 0..7
            float4 v = *(const float4*)(A + (size_t)(row0 + m) * 512 + k0 + kq * 4);
            As[kq*4+0][m] = v.x; As[kq*4+1][m] = v.y;
            As[kq*4+2][m] = v.z; As[kq*4+3][m] = v.w;
        }
        #pragma unroll
        for (int l = 0; l < 2; l++) {
            int t = tid + l * 256;
            int n = t & 63, kq = t >> 6;    // kq 0..7
            float4 v = *(const float4*)(W + (size_t)(col0 + n) * 512 + k0 + kq * 4);
            Ws[kq*4+0][n] = v.x; Ws[kq*4+1][n] = v.y;
            Ws[kq*4+2][n] = v.z; Ws[kq*4+3][n] = v.w;
        }
        __syncthreads();
        #pragma unroll
        for (int k = 0; k < GBK; k++) {
            float4 a0 = *(const float4*)&As[k][m0];
            float4 a1 = *(const float4*)&As[k][m0 + 4];
            float4 wv = *(const float4*)&Ws[k][n0];
            unsigned long long w01, w23;
            PACK2(w01, wv.x, wv.y);
            PACK2(w23, wv.z, wv.w);
            float am[8] = {a0.x,a0.y,a0.z,a0.w,a1.x,a1.y,a1.z,a1.w};
            #pragma unroll
            for (int i = 0; i < 8; i++) {
                unsigned long long ai;
                BCAST2(ai, am[i]);
                FMA2(acc[i][0], ai, w01);
                FMA2(acc[i][1], ai, w23);
            }
        }
        __syncthreads();
    }
    float bv0 = 0.f, bv1 = 0.f, bv2 = 0.f, bv3 = 0.f;
    if (bias) {
        bv0 = bias[col0+n0]; bv1 = bias[col0+n0+1];
        bv2 = bias[col0+n0+2]; bv3 = bias[col0+n0+3];
    }
    #pragma unroll
    for (int i = 0; i < 8; i++) {
        float c0, c1, c2, c3;
        UNPK2(c0, c1, acc[i][0]);
        UNPK2(c2, c3, acc[i][1]);
        float4 o = {c0 + bv0, c1 + bv1, c2 + bv2, c3 + bv3};
        if (act == 1) {
            o.x = fminf(1.f, fmaxf(-1.f, o.x));
            o.y = fminf(1.f, fmaxf(-1.f, o.y));
            o.z = fminf(1.f, fmaxf(-1.f, o.z));
            o.w = fminf(1.f, fmaxf(-1.f, o.w));
        }
        *(float4*)(C + (size_t)(row0 + m0 + i) * N + col0 + n0) = o;
    }
}

// ======== GRU persistent recurrence (barrier-free, chunk-pipelined) =========
// grid=128 CTAs (single wave), 256 thr. CTA c owns h-columns j in [4c,4c+4).
// CTA group q = CTAs [32q,32q+32) produces k-chunk [128q,128q+128).
// After writing h at step s, each CTA bumps its group counter; the dot at
// step s+1 waits per-chunk (counter >= 32*(s+1)), staged by 64-thread quarters.
// Old h carried in registers; h double-buffered by step parity (skew-safe:
// writing h(s+2) requires having consumed all of h(s+1), which required every
// CTA to have consumed h(s)).
// smem: hs[512][32] (64KB) | wp[512][2][4] f32x2 pairs (32KB) | red (6KB) | bh
#define SM_HS   0
#define SM_WP   65536
#define SM_RED  (65536 + 32768)
#define SM_BH   (65536 + 32768 + 6144)
#define GRU_SMEM (65536 + 32768 + 6144 + 64)

__global__ __launch_bounds__(256)
void gru_kernel(const float* __restrict__ gi, const float* __restrict__ Whh,
                const float* __restrict__ bhh, float* __restrict__ st_out,
                int lay1) {
    extern __shared__ char sm[];
    float* hs = (float*)(sm + SM_HS);                      // [k*32 + b]
    unsigned long long* wp = (unsigned long long*)(sm + SM_WP);  // [k*8 + jp*4 + g]
    float2* red = (float2*)(sm + SM_RED);                  // [((ks*32+b)*2+jp)*3 + g]
    float* bh = (float*)(sm + SM_BH);                      // [12]
    const int tid = threadIdx.x;
    const int cta = blockIdx.x;

    unsigned* grp = lay1 ? g_grpB : g_grpA;
    // reset the OTHER layer's counters (only touched by the previous launch)
    if (cta < 4 && tid == 0) (lay1 ? g_grpA : g_grpB)[cta * 32] = 0;

    // Pack W_hh slice once: pair rows (j, j+1) within gate g, pair index jp.
    #pragma unroll
    for (int r = 0; r < 12; r++) {
        int g = r >> 2, jl = r & 3, jp = jl >> 1, sel = jl & 1;
        int rowg = g * 512 + cta * 4 + jl;
        for (int k = tid; k < 512; k += 256)
            ((float*)&wp[(size_t)k * 8 + jp * 4 + g])[sel] = Whh[(size_t)rowg * 512 + k];
    }
    if (tid < 12) {
        int g = tid >> 2, jl = tid & 3;
        bh[tid] = bhh[g * 512 + cta * 4 + jl];
    }
    __syncthreads();

    const int b = tid & 31, jp = (tid >> 5) & 1, ks = tid >> 6;  // quarter id
    const int cq = (ks + cta) & 3;       // chunk this quarter consumes (rotated)
    const int kbeg = cq * 128;
    const int t64 = tid & 63;
    const int myg = cta >> 5;            // group this CTA reports to
    // gate-phase identity (tid < 128)
    const int bb = tid & 31, jl = (tid >> 5) & 3;
    const int jg = cta * 4 + jl;

    // prefetch gi for step 0; old-h register
    float giv0 = 0.f, giv1 = 0.f, giv2 = 0.f, ho = 0.f;
    if (tid < 128) {
        giv0 = __ldg(gi + (size_t)bb * G3 + jg);
        giv1 = __ldg(gi + (size_t)bb * G3 + 512 + jg);
        giv2 = __ldg(gi + (size_t)bb * G3 + 1024 + jg);
    }

    for (int s = 0; s < 128; s++) {
        if (s > 0) {
            // ---- wait for this quarter's chunk producers (step s-1 done) ----
            if (t64 == 0) {
                unsigned tgt = 32u * (unsigned)s;
                while (ld_acq(&grp[cq * 32]) < tgt) { }
            }
            asm volatile("bar.sync %0, 64;" :: "r"(1 + ks));
            // ---- stage chunk cq from buffer (s-1)&1 ----
            {
                const float4* src = (const float4*)(g_hT2 + ((s + 1) & 1) * (Hn * Bn));
                float4* hs4 = (float4*)hs;
                #pragma unroll
                for (int l = 0; l < 16; l++) {
                    int idx = cq * 1024 + t64 + l * 64;
                    hs4[idx] = src[idx];
                }
            }
            asm volatile("bar.sync %0, 64;" :: "r"(1 + ks));

            // ---- partial dots over this chunk: 3 gate f32x2 accumulators ----
            unsigned long long a0 = 0ULL, a1 = 0ULL, a2 = 0ULL;
            const unsigned long long* wb = wp + jp * 4;
            #pragma unroll 4
            for (int kk = 0; kk < 128; kk++) {
                int k = kbeg + kk;
                float hk = hs[k * 32 + b];
                unsigned long long h2;
                BCAST2(h2, hk);
                ulonglong2 w01 = *(const ulonglong2*)(wb + (size_t)k * 8);
                unsigned long long w2v = wb[(size_t)k * 8 + 2];
                FMA2(a0, h2, w01.x);
                FMA2(a1, h2, w01.y);
                FMA2(a2, h2, w2v);
            }
            unsigned long long* rr = (unsigned long long*)&red[((ks * 32 + b) * 2 + jp) * 3];
            rr[0] = a0; rr[1] = a1; rr[2] = a2;
        }
        __syncthreads();

        // ---- gate math for the CTA's 4 columns ----
        if (tid < 128) {
            float gh0 = 0.f, gh1 = 0.f, gh2 = 0.f;
            if (s > 0) {
                int jpp = jl >> 1, sel = jl & 1;
                #pragma unroll
                for (int kk = 0; kk < 4; kk++) {
                    float2* q = &red[((kk * 32 + bb) * 2 + jpp) * 3];
                    float2 q0 = q[0], q1 = q[1], q2 = q[2];
                    gh0 += sel ? q0.y : q0.x;
                    gh1 += sel ? q1.y : q1.x;
                    gh2 += sel ? q2.y : q2.x;
                }
            }
            float r = 1.f / (1.f + expf(-(giv0 + gh0 + bh[jl])));
            float z = 1.f / (1.f + expf(-(giv1 + gh1 + bh[4 + jl])));
            float nn = tanhf(giv2 + r * (gh2 + bh[8 + jl]));
            float hn = (1.f - z) * nn + z * ho;
            ho = hn;
            g_hT2[(s & 1) * (Hn * Bn) + jg * 32 + bb] = hn;
            size_t oidx = lay1 ? ((size_t)bb * 128 + s) * 512 + jg
                               : ((size_t)s * 32 + bb) * 512 + jg;
            st_out[oidx] = hn;
        }
        __syncthreads();

        // ---- publish progress (release covers the CTA's h stores) ----
        if (tid == 0) red_release_add(&grp[myg * 32], 1);

        // ---- prefetch next step's gi (in flight over the next chunk waits) --
        if (s < 127 && tid < 128) {
            size_t gib = ((size_t)(s + 1) * 32 + bb) * (size_t)G3;
            giv0 = __ldg(gi + gib + jg);
            giv1 = __ldg(gi + gib + 512 + jg);
            giv2 = __ldg(gi + gib + 1024 + jg);
        }
    }
}

// ======== final: time-attention + linear + softmax ==========================
// states layout here: [b][s][h] (written directly by layer-1 GRU into d_out)
__global__ __launch_bounds__(256)
void final_kernel(const float* __restrict__ states, const float* __restrict__ attw,
                  const float* __restrict__ demoip, const float* __restrict__ linW,
                  const float* __restrict__ linb, float* __restrict__ out) {
    __shared__ float aw[512];
    __shared__ float lg[128];
    __shared__ float al[128];
    __shared__ float ctx[512];
    __shared__ float o10[10];
    const int tid = threadIdx.x, b = blockIdx.x;
    const int w = tid >> 5, lane = tid & 31;
    const float* stb = states + (size_t)b * 128 * 512;

    for (int h = tid; h < 512; h += 256) aw[h] = attw[h];
    __syncthreads();

    for (int s = w; s < 128; s += 8) {
        const float* row = stb + (size_t)s * 512;
        float acc = 0.f;
        for (int h = lane; h < 512; h += 32) acc += row[h] * aw[h];
        acc = wred(acc);
        if (lane == 0) lg[s] = acc;
    }
    __syncthreads();

    if (tid < 32) {
        float v[4]; float m = -1e30f;
        #pragma unroll
        for (int q = 0; q < 4; q++) { v[q] = lg[tid + q * 32]; m = fmaxf(m, v[q]); }
        #pragma unroll
        for (int o = 16; o; o >>= 1) m = fmaxf(m, __shfl_xor_sync(0xffffffffu, m, o));
        float ssum = 0.f;
        #pragma unroll
        for (int q = 0; q < 4; q++) { v[q] = expf(v[q] - m); ssum += v[q]; }
        ssum = wred(ssum);
        #pragma unroll
        for (int q = 0; q < 4; q++) {
            float a = v[q] / ssum;
            al[tid + q * 32] = a;
            out[OFF_AL + b * 128 + tid + q * 32] = a;
        }
    }
    __syncthreads();

    for (int h = tid; h < 512; h += 256) {
        float acc = 0.f;
        for (int s = 0; s < 128; s++) acc += al[s] * stb[(size_t)s * 512 + h];
        ctx[h] = acc;
        out[OFF_CTX + b * 512 + h] = acc;
    }
    __syncthreads();

    if (tid < 10) {
        float acc = linb[tid];
        const float* wrow = linW + tid * 515;
        for (int h = 0; h < 512; h++) acc += ctx[h] * wrow[h];
        for (int d = 0; d < 3; d++) acc += demoip[b * 3 + d] * wrow[512 + d];
        o10[tid] = acc;
    }
    __syncthreads();
    if (tid < 10) {
        float m = -1e30f;
        for (int o = 0; o < 10; o++) m = fmaxf(m, o10[o]);
        float e = expf(o10[tid] - m), ssum = 0.f;
        for (int o = 0; o < 10; o++) ssum += expf(o10[o] - m);
        out[OFF_OUT + b * 10 + tid] = e / ssum;
    }
}

// ======== launch ============================================================
extern "C" void kernel_launch(void* const* d_in, const int* in_sizes, int n_in,
                              void* d_out, int out_size) {
    // batch_size may or may not be materialized as input[2] (size-1 scalar).
    int sh = (in_sizes[2] == 1) ? 1 : 0;

    const float* inp   = (const float*)d_in[0];
    const float* demo  = (const float*)d_in[1];
    const float* convw = (const float*)d_in[2 + sh];
    // conv_b at [3+sh] cancels in the softmax; unused.
    const float* embW  = (const float*)d_in[4 + sh];
    const float* Wi0   = (const float*)d_in[5 + sh];
    const float* Wh0   = (const float*)d_in[6 + sh];
    const float* bi0   = (const float*)d_in[7 + sh];
    const float* bh0   = (const float*)d_in[8 + sh];
    const float* Wi1   = (const float*)d_in[9 + sh];
    const float* Wh1   = (const float*)d_in[10 + sh];
    const float* bi1   = (const float*)d_in[11 + sh];
    const float* bh1   = (const float*)d_in[12 + sh];
    const float* attw  = (const float*)d_in[13 + sh];
    const float* linW  = (const float*)d_in[14 + sh];
    const float* linb  = (const float*)d_in[15 + sh];
    float* out = (float*)d_out;

    cudaFuncSetAttribute(gru_kernel, cudaFuncAttributeMaxDynamicSharedMemorySize, GRU_SMEM);

    void *pc, *pe, *p0, *ps0, *p1;
    cudaGetSymbolAddress(&pc, g_conv);
    cudaGetSymbolAddress(&pe, g_emb);
    cudaGetSymbolAddress(&p0, g_gi0);
    cudaGetSymbolAddress(&ps0, g_st0);
    cudaGetSymbolAddress(&p1, g_gi1);

    conv_pool_kernel<<<Bn * Sn, 256>>>(inp, convw, (float*)pc);

    dim3 ge(In / GBN, (Sn * Bn) / GBM);   // (8, 32)
    dim3 gg(G3 / GBN, (Sn * Bn) / GBM);   // (24, 32)
    gemm_tn<<<ge, 256>>>((const float*)pc, embW, nullptr, (float*)pe, In, 1);
    gemm_tn<<<gg, 256>>>((const float*)pe, Wi0, bi0, (float*)p0, G3, 0);

    gru_kernel<<<128, 256, GRU_SMEM>>>((const float*)p0, Wh0, bh0, (float*)ps0, 0);

    gemm_tn<<<gg, 256>>>((const float*)ps0, Wi1, bi1, (float*)p1, G3, 0);

    gru_kernel<<<128, 256, GRU_SMEM>>>((const float*)p1, Wh1, bh1, out + OFF_ST, 1);

    final_kernel<<<Bn, 256>>>(out + OFF_ST, attw, demo, linW, linb, out);
}

// round 7
// speedup vs baseline: 1.4090x; 1.0749x over previous
#include <cuda_runtime.h>
#include <cuda_bf16.h>
#include <cstdint>
#include <cstddef>
#include <math.h>

// Dims
#define Bn 32
#define Sn 128
#define Pn 32
#define In 512
#define Hn 512
#define G3 1536
#define On 10

// Output layout: out[32,10] | states[32,128,512] | context[32,512] | alpha[32,128]
#define OFF_OUT 0
#define OFF_ST  320
#define OFF_CTX 2097472
#define OFF_AL  2113856

// -------- scratch (__device__ globals; no allocations allowed) --------------
__device__ float g_conv[Sn*Bn*In];
__device__ float g_emb [Sn*Bn*In];
__device__ float g_gi0 [Sn*Bn*G3];
__device__ float g_st0 [Sn*Bn*Hn];
__device__ float g_gi1 [Sn*Bn*G3];
__device__ float g_hT2[2*Hn*Bn];     // double-buffered h, transposed [k][b]
// per-group progress counters: group q (CTAs 32q..32q+31) at [q*32], separate lines.
// Two arrays, one per GRU layer; each layer resets the OTHER layer's array.
__device__ __align__(128) unsigned g_grpA[4*32];
__device__ __align__(128) unsigned g_grpB[4*32];

// -------- helpers -----------------------------------------------------------
__device__ __forceinline__ float wred(float v) {
    #pragma unroll
    for (int o = 16; o; o >>= 1) v += __shfl_xor_sync(0xffffffffu, v, o);
    return v;
}
__device__ __forceinline__ unsigned ld_acq(unsigned* p) {
    unsigned v;
    asm volatile("ld.acquire.gpu.u32 %0,[%1];" : "=r"(v) : "l"(p) : "memory");
    return v;
}
__device__ __forceinline__ void red_release_add(unsigned* p, unsigned v) {
    asm volatile("red.release.gpu.global.add.u32 [%0],%1;"
                 :: "l"(p), "r"(v) : "memory");
}
#define FMA2(d,a,b) asm("fma.rn.f32x2 %0,%1,%2,%0;" : "+l"(d) : "l"(a), "l"(b))
#define BCAST2(d,f) asm("mov.b64 %0,{%1,%1};" : "=l"(d) : "f"(f))
#define PACK2(d,x,y) asm("mov.b64 %0,{%1,%2};" : "=l"(d) : "f"(x), "f"(y))
#define UNPK2(x,y,d) asm("mov.b64 {%0,%1},%2;" : "=f"(x), "=f"(y) : "l"(d))

// ======== K1: conv-attention pooling over P (conv_b cancels in softmax) =====
__global__ __launch_bounds__(256)
void conv_pool_kernel(const float* __restrict__ in, const float* __restrict__ conv_w,
                      float* __restrict__ conv_all) {
    __shared__ float cw[In];
    __shared__ float sc[Pn];
    __shared__ float at[Pn];
    const int tid = threadIdx.x;
    const int bx = blockIdx.x;          // b*S + s
    const int b = bx >> 7, s = bx & 127;
    const float* base = in + (size_t)bx * (Pn * In);

    if (tid < 128) ((float4*)cw)[tid] = ((const float4*)conv_w)[tid];
    __syncthreads();

    const int w = tid >> 5, lane = tid & 31;
    #pragma unroll
    for (int q = 0; q < 4; q++) {
        int p = w * 4 + q;
        const float4* row = (const float4*)(base + (size_t)p * In);
        const float4* cw4 = (const float4*)cw;
        float acc = 0.f;
        for (int kk = lane; kk < 128; kk += 32) {
            float4 x = row[kk], y = cw4[kk];
            acc += x.x*y.x + x.y*y.y + x.z*y.z + x.w*y.w;
        }
        acc = wred(acc);
        if (lane == 0) sc[p] = acc;
    }
    __syncthreads();

    if (tid < 32) {
        float v = sc[tid], m = v;
        #pragma unroll
        for (int o = 16; o; o >>= 1) m = fmaxf(m, __shfl_xor_sync(0xffffffffu, m, o));
        float e = expf(v - m);
        float ssum = wred(e);
        at[tid] = e / ssum;
    }
    __syncthreads();

    float* dst = conv_all + ((size_t)s * Bn + b) * In;   // row = s*32+b
    for (int i = tid; i < In; i += 256) {
        float acc = 0.f;
        #pragma unroll 8
        for (int p = 0; p < Pn; p++) acc += at[p] * base[(size_t)p * In + i];
        dst[i] = acc;
    }
}

// ======== GEMM  C[M,N] = act(A[M,512] @ W[N,512]^T + bias) ==================
#define GBM 128
#define GBN 64
#define GBK 32
__global__ __launch_bounds__(256)
void gemm_tn(const float* __restrict__ A, const float* __restrict__ W,
             const float* __restrict__ bias, float* __restrict__ C,
             int N, int act) {
    __shared__ float As[GBK][GBM + 4];
    __shared__ float Ws[GBK][GBN + 4];
    const int tid = threadIdx.x;
    const int row0 = blockIdx.y * GBM;
    const int col0 = blockIdx.x * GBN;
    const int m0 = (tid >> 4) * 8;      // 0..120
    const int n0 = (tid & 15) * 4;      // 0..60
    unsigned long long acc[8][2];
    #pragma unroll
    for (int i = 0; i < 8; i++) { acc[i][0] = 0ULL; acc[i][1] = 0ULL; }

    for (int k0 = 0; k0 < 512; k0 += GBK) {
        #pragma unroll
        for (int l = 0; l < 4; l++) {
            int t = tid + l * 256;
            int m = t & 127, kq = t >> 7;   // kq 0..7
            float4 v = *(const float4*)(A + (size_t)(row0 + m) * 512 + k0 + kq * 4);
            As[kq*4+0][m] = v.x; As[kq*4+1][m] = v.y;
            As[kq*4+2][m] = v.z; As[kq*4+3][m] = v.w;
        }
        #pragma unroll
        for (int l = 0; l < 2; l++) {
            int t = tid + l * 256;
            int n = t & 63, kq = t >> 6;    // kq 0..7
            float4 v = *(const float4*)(W + (size_t)(col0 + n) * 512 + k0 + kq * 4);
            Ws[kq*4+0][n] = v.x; Ws[kq*4+1][n] = v.y;
            Ws[kq*4+2][n] = v.z; Ws[kq*4+3][n] = v.w;
        }
        __syncthreads();
        #pragma unroll
        for (int k = 0; k < GBK; k++) {
            float4 a0 = *(const float4*)&As[k][m0];
            float4 a1 = *(const float4*)&As[k][m0 + 4];
            float4 wv = *(const float4*)&Ws[k][n0];
            unsigned long long w01, w23;
            PACK2(w01, wv.x, wv.y);
            PACK2(w23, wv.z, wv.w);
            float am[8] = {a0.x,a0.y,a0.z,a0.w,a1.x,a1.y,a1.z,a1.w};
            #pragma unroll
            for (int i = 0; i < 8; i++) {
                unsigned long long ai;
                BCAST2(ai, am[i]);
                FMA2(acc[i][0], ai, w01);
                FMA2(acc[i][1], ai, w23);
            }
        }
        __syncthreads();
    }
    float bv0 = 0.f, bv1 = 0.f, bv2 = 0.f, bv3 = 0.f;
    if (bias) {
        bv0 = bias[col0+n0]; bv1 = bias[col0+n0+1];
        bv2 = bias[col0+n0+2]; bv3 = bias[col0+n0+3];
    }
    #pragma unroll
    for (int i = 0; i < 8; i++) {
        float c0, c1, c2, c3;
        UNPK2(c0, c1, acc[i][0]);
        UNPK2(c2, c3, acc[i][1]);
        float4 o = {c0 + bv0, c1 + bv1, c2 + bv2, c3 + bv3};
        if (act == 1) {
            o.x = fminf(1.f, fmaxf(-1.f, o.x));
            o.y = fminf(1.f, fmaxf(-1.f, o.y));
            o.z = fminf(1.f, fmaxf(-1.f, o.z));
            o.w = fminf(1.f, fmaxf(-1.f, o.w));
        }
        *(float4*)(C + (size_t)(row0 + m0 + i) * N + col0 + n0) = o;
    }
}

// ======== GRU persistent recurrence (barrier-free, warp-autonomous) =========
// grid=128 CTAs, 512 thr (16 warps). CTA c owns h-columns [4c,4c+4) (12 gate cols).
// Warp w: lane=b, k-slice = chunk q*128 + (w&3)*32 where q=((w>>2)+cta)&3.
// Each warp: poll its chunk flag -> LDG 32 h direct from L2 (MLP=32) ->
// 12-col dot (6 f32x2 accs; 1 h feeds 6 FMA2) -> smem reduce (pad-13 rows).
// h double-buffered by parity; old h in register. 2 syncthreads/step, 0 named bars.
#define SM_WP   0
#define SM_RED  32768
#define SM_BH   (32768 + 26624)
#define GRU_SMEM (32768 + 26624 + 64)

__global__ __launch_bounds__(512)
void gru_kernel(const float* __restrict__ gi, const float* __restrict__ Whh,
                const float* __restrict__ bhh, float* __restrict__ st_out,
                int lay1) {
    extern __shared__ char sm[];
    float* wp  = (float*)(sm + SM_WP);    // [k][16] floats; cols c=0..11 (c=g*4+jl)
    float* red = (float*)(sm + SM_RED);   // [(w*32+b)*13 + c]
    float* bh  = (float*)(sm + SM_BH);    // [12]
    const int tid = threadIdx.x;
    const int cta = blockIdx.x;

    unsigned* grp = lay1 ? g_grpB : g_grpA;
    // reset the OTHER layer's counters (only touched by the previous launch)
    if (cta < 4 && tid == 0) (lay1 ? g_grpA : g_grpB)[cta * 32] = 0;

    // weights: wp[k*16 + c] = Whh[(g*512 + cta*4 + jl)*512 + k], c = g*4+jl
    for (int i = tid; i < 6144; i += 512) {
        int c = i >> 9, k = i & 511;
        int g = c >> 2, jl = c & 3;
        wp[k * 16 + c] = Whh[(size_t)(g * 512 + cta * 4 + jl) * 512 + k];
    }
    if (tid < 12) bh[tid] = bhh[(tid >> 2) * 512 + cta * 4 + (tid & 3)];
    __syncthreads();

    const int lane = tid & 31, w = tid >> 5;
    const int q = ((w >> 2) + cta) & 3;          // chunk this warp consumes
    const int k0 = q * 128 + (w & 3) * 32;       // warp's 32-k slice
    const int myg = cta >> 5;
    // gate-phase identity (tid < 128)
    const int bb = tid & 31, jl = (tid >> 5) & 3;
    const int jg = cta * 4 + jl;

    float giv0 = 0.f, giv1 = 0.f, giv2 = 0.f, ho = 0.f;
    if (tid < 128) {
        giv0 = __ldg(gi + (size_t)bb * G3 + jg);
        giv1 = __ldg(gi + (size_t)bb * G3 + 512 + jg);
        giv2 = __ldg(gi + (size_t)bb * G3 + 1024 + jg);
    }

    for (int s = 0; s < 128; s++) {
        if (s > 0) {
            // ---- warp-autonomous wait for this chunk's 32 producers ----
            if (lane == 0) {
                unsigned tgt = 32u * (unsigned)s;
                while (ld_acq(&grp[q * 32]) < tgt) { }
            }
            __syncwarp();

            // ---- direct L2 read: all 32 h loads in flight at once ----
            const float* hb = g_hT2 + ((s + 1) & 1) * (Hn * Bn) + (size_t)k0 * 32 + lane;
            float hr[32];
            #pragma unroll
            for (int i = 0; i < 32; i++) hr[i] = hb[i * 32];

            unsigned long long acc[6];
            #pragma unroll
            for (int p = 0; p < 6; p++) acc[p] = 0ULL;
            #pragma unroll
            for (int i = 0; i < 32; i++) {
                unsigned long long h2;
                BCAST2(h2, hr[i]);
                const ulonglong2* wk = (const ulonglong2*)(wp + (k0 + i) * 16);
                ulonglong2 A = wk[0], Bv = wk[1], Cv = wk[2];
                FMA2(acc[0], h2, A.x);  FMA2(acc[1], h2, A.y);
                FMA2(acc[2], h2, Bv.x); FMA2(acc[3], h2, Bv.y);
                FMA2(acc[4], h2, Cv.x); FMA2(acc[5], h2, Cv.y);
            }
            float* rr = red + (w * 32 + lane) * 13;
            #pragma unroll
            for (int p = 0; p < 6; p++) {
                float x, y;
                UNPK2(x, y, acc[p]);
                rr[2 * p] = x; rr[2 * p + 1] = y;
            }
        }
        __syncthreads();

        // ---- gate math for the CTA's 4 columns ----
        if (tid < 128) {
            float gh0 = 0.f, gh1 = 0.f, gh2 = 0.f;
            if (s > 0) {
                #pragma unroll
                for (int ww = 0; ww < 16; ww++) {
                    const float* rr = red + (ww * 32 + bb) * 13;
                    gh0 += rr[jl];
                    gh1 += rr[4 + jl];
                    gh2 += rr[8 + jl];
                }
            }
            float r = 1.f / (1.f + expf(-(giv0 + gh0 + bh[jl])));
            float z = 1.f / (1.f + expf(-(giv1 + gh1 + bh[4 + jl])));
            float nn = tanhf(giv2 + r * (gh2 + bh[8 + jl]));
            float hn = (1.f - z) * nn + z * ho;
            ho = hn;
            g_hT2[(s & 1) * (Hn * Bn) + jg * 32 + bb] = hn;
            size_t oidx = lay1 ? ((size_t)bb * 128 + s) * 512 + jg
                               : ((size_t)s * 32 + bb) * 512 + jg;
            st_out[oidx] = hn;
        }
        __syncthreads();

        // ---- publish progress (release covers the CTA's h stores) ----
        if (tid == 0) red_release_add(&grp[myg * 32], 1);

        // ---- prefetch next step's gi (hides under next flag wait) ----
        if (s < 127 && tid < 128) {
            size_t gib = ((size_t)(s + 1) * 32 + bb) * (size_t)G3;
            giv0 = __ldg(gi + gib + jg);
            giv1 = __ldg(gi + gib + 512 + jg);
            giv2 = __ldg(gi + gib + 1024 + jg);
        }
    }
}

// ======== final: time-attention + linear + softmax ==========================
// states layout here: [b][s][h] (written directly by layer-1 GRU into d_out)
__global__ __launch_bounds__(256)
void final_kernel(const float* __restrict__ states, const float* __restrict__ attw,
                  const float* __restrict__ demoip, const float* __restrict__ linW,
                  const float* __restrict__ linb, float* __restrict__ out) {
    __shared__ float aw[512];
    __shared__ float lg[128];
    __shared__ float al[128];
    __shared__ float ctx[512];
    __shared__ float o10[10];
    const int tid = threadIdx.x, b = blockIdx.x;
    const int w = tid >> 5, lane = tid & 31;
    const float* stb = states + (size_t)b * 128 * 512;

    for (int h = tid; h < 512; h += 256) aw[h] = attw[h];
    __syncthreads();

    for (int s = w; s < 128; s += 8) {
        const float* row = stb + (size_t)s * 512;
        float acc = 0.f;
        for (int h = lane; h < 512; h += 32) acc += row[h] * aw[h];
        acc = wred(acc);
        if (lane == 0) lg[s] = acc;
    }
    __syncthreads();

    if (tid < 32) {
        float v[4]; float m = -1e30f;
        #pragma unroll
        for (int q = 0; q < 4; q++) { v[q] = lg[tid + q * 32]; m = fmaxf(m, v[q]); }
        #pragma unroll
        for (int o = 16; o; o >>= 1) m = fmaxf(m, __shfl_xor_sync(0xffffffffu, m, o));
        float ssum = 0.f;
        #pragma unroll
        for (int q = 0; q < 4; q++) { v[q] = expf(v[q] - m); ssum += v[q]; }
        ssum = wred(ssum);
        #pragma unroll
        for (int q = 0; q < 4; q++) {
            float a = v[q] / ssum;
            al[tid + q * 32] = a;
            out[OFF_AL + b * 128 + tid + q * 32] = a;
        }
    }
    __syncthreads();

    for (int h = tid; h < 512; h += 256) {
        float acc = 0.f;
        for (int s = 0; s < 128; s++) acc += al[s] * stb[(size_t)s * 512 + h];
        ctx[h] = acc;
        out[OFF_CTX + b * 512 + h] = acc;
    }
    __syncthreads();

    if (tid < 10) {
        float acc = linb[tid];
        const float* wrow = linW + tid * 515;
        for (int h = 0; h < 512; h++) acc += ctx[h] * wrow[h];
        for (int d = 0; d < 3; d++) acc += demoip[b * 3 + d] * wrow[512 + d];
        o10[tid] = acc;
    }
    __syncthreads();
    if (tid < 10) {
        float m = -1e30f;
        for (int o = 0; o < 10; o++) m = fmaxf(m, o10[o]);
        float e = expf(o10[tid] - m), ssum = 0.f;
        for (int o = 0; o < 10; o++) ssum += expf(o10[o] - m);
        out[OFF_OUT + b * 10 + tid] = e / ssum;
    }
}

// ======== launch ============================================================
extern "C" void kernel_launch(void* const* d_in, const int* in_sizes, int n_in,
                              void* d_out, int out_size) {
    // batch_size may or may not be materialized as input[2] (size-1 scalar).
    int sh = (in_sizes[2] == 1) ? 1 : 0;

    const float* inp   = (const float*)d_in[0];
    const float* demo  = (const float*)d_in[1];
    const float* convw = (const float*)d_in[2 + sh];
    // conv_b at [3+sh] cancels in the softmax; unused.
    const float* embW  = (const float*)d_in[4 + sh];
    const float* Wi0   = (const float*)d_in[5 + sh];
    const float* Wh0   = (const float*)d_in[6 + sh];
    const float* bi0   = (const float*)d_in[7 + sh];
    const float* bh0   = (const float*)d_in[8 + sh];
    const float* Wi1   = (const float*)d_in[9 + sh];
    const float* Wh1   = (const float*)d_in[10 + sh];
    const float* bi1   = (const float*)d_in[11 + sh];
    const float* bh1   = (const float*)d_in[12 + sh];
    const float* attw  = (const float*)d_in[13 + sh];
    const float* linW  = (const float*)d_in[14 + sh];
    const float* linb  = (const float*)d_in[15 + sh];
    float* out = (float*)d_out;

    cudaFuncSetAttribute(gru_kernel, cudaFuncAttributeMaxDynamicSharedMemorySize, GRU_SMEM);

    void *pc, *pe, *p0, *ps0, *p1;
    cudaGetSymbolAddress(&pc, g_conv);
    cudaGetSymbolAddress(&pe, g_emb);
    cudaGetSymbolAddress(&p0, g_gi0);
    cudaGetSymbolAddress(&ps0, g_st0);
    cudaGetSymbolAddress(&p1, g_gi1);

    conv_pool_kernel<<<Bn * Sn, 256>>>(inp, convw, (float*)pc);

    dim3 ge(In / GBN, (Sn * Bn) / GBM);   // (8, 32)
    dim3 gg(G3 / GBN, (Sn * Bn) / GBM);   // (24, 32)
    gemm_tn<<<ge, 256>>>((const float*)pc, embW, nullptr, (float*)pe, In, 1);
    gemm_tn<<<gg, 256>>>((const float*)pe, Wi0, bi0, (float*)p0, G3, 0);

    gru_kernel<<<128, 512, GRU_SMEM>>>((const float*)p0, Wh0, bh0, (float*)ps0, 0);

    gemm_tn<<<gg, 256>>>((const float*)ps0, Wi1, bi1, (float*)p1, G3, 0);

    gru_kernel<<<128, 512, GRU_SMEM>>>((const float*)p1, Wh1, bh1, out + OFF_ST, 1);

    final_kernel<<<Bn, 256>>>(out + OFF_ST, attw, demo, linW, linb, out);
}

// round 8
// speedup vs baseline: 1.7460x; 1.2391x over previous
#include <cuda_runtime.h>
#include <cuda_bf16.h>
#include <cstdint>
#include <cstddef>
#include <math.h>

// Dims
#define Bn 32
#define Sn 128
#define Pn 32
#define In 512
#define Hn 512
#define G3 1536
#define On 10

// Output layout: out[32,10] | states[32,128,512] | context[32,512] | alpha[32,128]
#define OFF_OUT 0
#define OFF_ST  320
#define OFF_CTX 2097472
#define OFF_AL  2113856

// -------- scratch (__device__ globals; no allocations allowed) --------------
__device__ float g_conv[Sn*Bn*In];
__device__ float g_emb [Sn*Bn*In];
__device__ float g_gi0 [Sn*Bn*G3];
__device__ float g_st0 [Sn*Bn*Hn];
__device__ float g_gi1 [Sn*Bn*G3];
__device__ float g_hT2[2*Hn*Bn];     // double-buffered h, transposed [k][b]
// per-CTA step flags, each on its own 128B line. Two arrays (one per layer);
// each layer resets the OTHER layer's array (stream-ordered, race-free).
__device__ __align__(128) unsigned g_flagA[128*32];
__device__ __align__(128) unsigned g_flagB[128*32];

// -------- helpers -----------------------------------------------------------
__device__ __forceinline__ float wred(float v) {
    #pragma unroll
    for (int o = 16; o; o >>= 1) v += __shfl_xor_sync(0xffffffffu, v, o);
    return v;
}
__device__ __forceinline__ unsigned ld_acq(const unsigned* p) {
    unsigned v;
    asm volatile("ld.acquire.gpu.u32 %0,[%1];" : "=r"(v) : "l"(p) : "memory");
    return v;
}
__device__ __forceinline__ void st_rel(unsigned* p, unsigned v) {
    asm volatile("st.release.gpu.u32 [%0],%1;" :: "l"(p), "r"(v) : "memory");
}
__device__ __forceinline__ float ldcg(const float* p) {
    float v;
    asm volatile("ld.global.cg.f32 %0,[%1];" : "=f"(v) : "l"(p));
    return v;
}
#define FMA2(d,a,b) asm("fma.rn.f32x2 %0,%1,%2,%0;" : "+l"(d) : "l"(a), "l"(b))
#define BCAST2(d,f) asm("mov.b64 %0,{%1,%1};" : "=l"(d) : "f"(f))
#define PACK2(d,x,y) asm("mov.b64 %0,{%1,%2};" : "=l"(d) : "f"(x), "f"(y))
#define UNPK2(x,y,d) asm("mov.b64 {%0,%1},%2;" : "=f"(x), "=f"(y) : "l"(d))

// ======== K1: conv-attention pooling over P (conv_b cancels in softmax) =====
__global__ __launch_bounds__(256)
void conv_pool_kernel(const float* __restrict__ in, const float* __restrict__ conv_w,
                      float* __restrict__ conv_all) {
    __shared__ float cw[In];
    __shared__ float sc[Pn];
    __shared__ float at[Pn];
    const int tid = threadIdx.x;
    const int bx = blockIdx.x;          // b*S + s
    const int b = bx >> 7, s = bx & 127;
    const float* base = in + (size_t)bx * (Pn * In);

    if (tid < 128) ((float4*)cw)[tid] = ((const float4*)conv_w)[tid];
    __syncthreads();

    const int w = tid >> 5, lane = tid & 31;
    #pragma unroll
    for (int q = 0; q < 4; q++) {
        int p = w * 4 + q;
        const float4* row = (const float4*)(base + (size_t)p * In);
        const float4* cw4 = (const float4*)cw;
        float acc = 0.f;
        for (int kk = lane; kk < 128; kk += 32) {
            float4 x = row[kk], y = cw4[kk];
            acc += x.x*y.x + x.y*y.y + x.z*y.z + x.w*y.w;
        }
        acc = wred(acc);
        if (lane == 0) sc[p] = acc;
    }
    __syncthreads();

    if (tid < 32) {
        float v = sc[tid], m = v;
        #pragma unroll
        for (int o = 16; o; o >>= 1) m = fmaxf(m, __shfl_xor_sync(0xffffffffu, m, o));
        float e = expf(v - m);
        float ssum = wred(e);
        at[tid] = e / ssum;
    }
    __syncthreads();

    float* dst = conv_all + ((size_t)s * Bn + b) * In;   // row = s*32+b
    for (int i = tid; i < In; i += 256) {
        float acc = 0.f;
        #pragma unroll 8
        for (int p = 0; p < Pn; p++) acc += at[p] * base[(size_t)p * In + i];
        dst[i] = acc;
    }
}

// ======== GEMM  C[M,N] = act(A[M,512] @ W[N,512]^T + bias) ==================
#define GBM 128
#define GBN 64
#define GBK 32
__global__ __launch_bounds__(256)
void gemm_tn(const float* __restrict__ A, const float* __restrict__ W,
             const float* __restrict__ bias, float* __restrict__ C,
             int N, int act) {
    __shared__ float As[GBK][GBM + 4];
    __shared__ float Ws[GBK][GBN + 4];
    const int tid = threadIdx.x;
    const int row0 = blockIdx.y * GBM;
    const int col0 = blockIdx.x * GBN;
    const int m0 = (tid >> 4) * 8;      // 0..120
    const int n0 = (tid & 15) * 4;      // 0..60
    unsigned long long acc[8][2];
    #pragma unroll
    for (int i = 0; i < 8; i++) { acc[i][0] = 0ULL; acc[i][1] = 0ULL; }

    for (int k0 = 0; k0 < 512; k0 += GBK) {
        #pragma unroll
        for (int l = 0; l < 4; l++) {
            int t = tid + l * 256;
            int m = t & 127, kq = t >> 7;   // kq 0..7
            float4 v = *(const float4*)(A + (size_t)(row0 + m) * 512 + k0 + kq * 4);
            As[kq*4+0][m] = v.x; As[kq*4+1][m] = v.y;
            As[kq*4+2][m] = v.z; As[kq*4+3][m] = v.w;
        }
        #pragma unroll
        for (int l = 0; l < 2; l++) {
            int t = tid + l * 256;
            int n = t & 63, kq = t >> 6;    // kq 0..7
            float4 v = *(const float4*)(W + (size_t)(col0 + n) * 512 + k0 + kq * 4);
            Ws[kq*4+0][n] = v.x; Ws[kq*4+1][n] = v.y;
            Ws[kq*4+2][n] = v.z; Ws[kq*4+3][n] = v.w;
        }
        __syncthreads();
        #pragma unroll
        for (int k = 0; k < GBK; k++) {
            float4 a0 = *(const float4*)&As[k][m0];
            float4 a1 = *(const float4*)&As[k][m0 + 4];
            float4 wv = *(const float4*)&Ws[k][n0];
            unsigned long long w01, w23;
            PACK2(w01, wv.x, wv.y);
            PACK2(w23, wv.z, wv.w);
            float am[8] = {a0.x,a0.y,a0.z,a0.w,a1.x,a1.y,a1.z,a1.w};
            #pragma unroll
            for (int i = 0; i < 8; i++) {
                unsigned long long ai;
                BCAST2(ai, am[i]);
                FMA2(acc[i][0], ai, w01);
                FMA2(acc[i][1], ai, w23);
            }
        }
        __syncthreads();
    }
    float bv0 = 0.f, bv1 = 0.f, bv2 = 0.f, bv3 = 0.f;
    if (bias) {
        bv0 = bias[col0+n0]; bv1 = bias[col0+n0+1];
        bv2 = bias[col0+n0+2]; bv3 = bias[col0+n0+3];
    }
    #pragma unroll
    for (int i = 0; i < 8; i++) {
        float c0, c1, c2, c3;
        UNPK2(c0, c1, acc[i][0]);
        UNPK2(c2, c3, acc[i][1]);
        float4 o = {c0 + bv0, c1 + bv1, c2 + bv2, c3 + bv3};
        if (act == 1) {
            o.x = fminf(1.f, fmaxf(-1.f, o.x));
            o.y = fminf(1.f, fmaxf(-1.f, o.y));
            o.z = fminf(1.f, fmaxf(-1.f, o.z));
            o.w = fminf(1.f, fmaxf(-1.f, o.w));
        }
        *(float4*)(C + (size_t)(row0 + m0 + i) * N + col0 + n0) = o;
    }
}

// ======== GRU persistent recurrence (single-writer flags, leader polls) =====
// grid=128 CTAs, 512 thr (16 warps). CTA c owns h-columns [4c,4c+4) (12 gate cols).
// Warp w: lane=b, k-slice = chunk q*128 + (w&3)*32 where q=((w>>2)+cta)&3.
// Sync: per-CTA flag line; producer tid0 does ONE st.release (no atomics).
// Leader warp of each 4-warp chunk group reads the chunk's 32 producer flags
// across lanes (+__all_sync), then bar.sync(1+group,128) releases the group.
// h read via ld.global.cg (L1-bypassing: coherent + no L1 pollution).
#define SM_WP   0
#define SM_RED  32768
#define SM_BH   (32768 + 26624)
#define GRU_SMEM (32768 + 26624 + 64)

__global__ __launch_bounds__(512)
void gru_kernel(const float* __restrict__ gi, const float* __restrict__ Whh,
                const float* __restrict__ bhh, float* __restrict__ st_out,
                int lay1) {
    extern __shared__ char sm[];
    float* wp  = (float*)(sm + SM_WP);    // [k][16] floats; cols c=0..11 (c=g*4+jl)
    float* red = (float*)(sm + SM_RED);   // [(w*32+b)*13 + c]
    float* bh  = (float*)(sm + SM_BH);    // [12]
    const int tid = threadIdx.x;
    const int cta = blockIdx.x;

    unsigned* flg = lay1 ? g_flagB : g_flagA;
    // reset the OTHER layer's flag (only touched by the previous launch)
    if (tid == 0) (lay1 ? g_flagA : g_flagB)[cta * 32] = 0;

    // weights: wp[k*16 + c] = Whh[(g*512 + cta*4 + jl)*512 + k], c = g*4+jl
    for (int i = tid; i < 6144; i += 512) {
        int c = i >> 9, k = i & 511;
        int g = c >> 2, jl = c & 3;
        wp[k * 16 + c] = Whh[(size_t)(g * 512 + cta * 4 + jl) * 512 + k];
    }
    if (tid < 12) bh[tid] = bhh[(tid >> 2) * 512 + cta * 4 + (tid & 3)];
    __syncthreads();

    const int lane = tid & 31, w = tid >> 5;
    const int gq = w >> 2;                       // chunk group 0..3 (warps 4gq..4gq+3)
    const int q = (gq + cta) & 3;                // chunk this group consumes
    const int k0 = q * 128 + (w & 3) * 32;       // warp's 32-k slice
    // gate-phase identity (tid < 128)
    const int bb = tid & 31, jl = (tid >> 5) & 3;
    const int jg = cta * 4 + jl;

    float giv0 = 0.f, giv1 = 0.f, giv2 = 0.f, ho = 0.f;
    if (tid < 128) {
        giv0 = __ldg(gi + (size_t)bb * G3 + jg);
        giv1 = __ldg(gi + (size_t)bb * G3 + 512 + jg);
        giv2 = __ldg(gi + (size_t)bb * G3 + 1024 + jg);
    }

    for (int s = 0; s < 128; s++) {
        if (s > 0) {
            // ---- leader warp polls this chunk's 32 producer flags ----
            if ((w & 3) == 0) {
                const unsigned* fp = &flg[(q * 32 + lane) * 32];
                unsigned tgt = (unsigned)s;
                while (!__all_sync(0xffffffffu, ld_acq(fp) >= tgt)) { }
            }
            asm volatile("bar.sync %0, 128;" :: "r"(1 + gq));

            // ---- direct L2 read (cg): all 32 h loads in flight at once ----
            const float* hb = g_hT2 + ((s + 1) & 1) * (Hn * Bn) + (size_t)k0 * 32 + lane;
            float hr[32];
            #pragma unroll
            for (int i = 0; i < 32; i++) hr[i] = ldcg(hb + i * 32);

            unsigned long long acc[6];
            #pragma unroll
            for (int p = 0; p < 6; p++) acc[p] = 0ULL;
            #pragma unroll
            for (int i = 0; i < 32; i++) {
                unsigned long long h2;
                BCAST2(h2, hr[i]);
                const ulonglong2* wk = (const ulonglong2*)(wp + (k0 + i) * 16);
                ulonglong2 A = wk[0], Bv = wk[1], Cv = wk[2];
                FMA2(acc[0], h2, A.x);  FMA2(acc[1], h2, A.y);
                FMA2(acc[2], h2, Bv.x); FMA2(acc[3], h2, Bv.y);
                FMA2(acc[4], h2, Cv.x); FMA2(acc[5], h2, Cv.y);
            }
            float* rr = red + (w * 32 + lane) * 13;
            #pragma unroll
            for (int p = 0; p < 6; p++) {
                float x, y;
                UNPK2(x, y, acc[p]);
                rr[2 * p] = x; rr[2 * p + 1] = y;
            }
        }
        __syncthreads();

        // ---- gate math for the CTA's 4 columns ----
        float hn = 0.f;
        if (tid < 128) {
            float gh0 = 0.f, gh1 = 0.f, gh2 = 0.f;
            if (s > 0) {
                #pragma unroll
                for (int ww = 0; ww < 16; ww++) {
                    const float* rr = red + (ww * 32 + bb) * 13;
                    gh0 += rr[jl];
                    gh1 += rr[4 + jl];
                    gh2 += rr[8 + jl];
                }
            }
            float r = 1.f / (1.f + expf(-(giv0 + gh0 + bh[jl])));
            float z = 1.f / (1.f + expf(-(giv1 + gh1 + bh[4 + jl])));
            float nn = tanhf(giv2 + r * (gh2 + bh[8 + jl]));
            hn = (1.f - z) * nn + z * ho;
            ho = hn;
            g_hT2[(s & 1) * (Hn * Bn) + jg * 32 + bb] = hn;
        }
        __syncthreads();

        // ---- publish progress: ONE release store, no atomics ----
        if (tid == 0) st_rel(&flg[cta * 32], (unsigned)(s + 1));

        // ---- off-critical-path work: states write + next gi prefetch ----
        if (tid < 128) {
            size_t oidx = lay1 ? ((size_t)bb * 128 + s) * 512 + jg
                               : ((size_t)s * 32 + bb) * 512 + jg;
            st_out[oidx] = hn;
            if (s < 127) {
                size_t gib = ((size_t)(s + 1) * 32 + bb) * (size_t)G3;
                giv0 = __ldg(gi + gib + jg);
                giv1 = __ldg(gi + gib + 512 + jg);
                giv2 = __ldg(gi + gib + 1024 + jg);
            }
        }
    }
}

// ======== final: time-attention + linear + softmax ==========================
// states layout here: [b][s][h] (written directly by layer-1 GRU into d_out)
__global__ __launch_bounds__(256)
void final_kernel(const float* __restrict__ states, const float* __restrict__ attw,
                  const float* __restrict__ demoip, const float* __restrict__ linW,
                  const float* __restrict__ linb, float* __restrict__ out) {
    __shared__ float aw[512];
    __shared__ float lg[128];
    __shared__ float al[128];
    __shared__ float ctx[512];
    __shared__ float o10[10];
    const int tid = threadIdx.x, b = blockIdx.x;
    const int w = tid >> 5, lane = tid & 31;
    const float* stb = states + (size_t)b * 128 * 512;

    for (int h = tid; h < 512; h += 256) aw[h] = attw[h];
    __syncthreads();

    for (int s = w; s < 128; s += 8) {
        const float* row = stb + (size_t)s * 512;
        float acc = 0.f;
        for (int h = lane; h < 512; h += 32) acc += row[h] * aw[h];
        acc = wred(acc);
        if (lane == 0) lg[s] = acc;
    }
    __syncthreads();

    if (tid < 32) {
        float v[4]; float m = -1e30f;
        #pragma unroll
        for (int q = 0; q < 4; q++) { v[q] = lg[tid + q * 32]; m = fmaxf(m, v[q]); }
        #pragma unroll
        for (int o = 16; o; o >>= 1) m = fmaxf(m, __shfl_xor_sync(0xffffffffu, m, o));
        float ssum = 0.f;
        #pragma unroll
        for (int q = 0; q < 4; q++) { v[q] = expf(v[q] - m); ssum += v[q]; }
        ssum = wred(ssum);
        #pragma unroll
        for (int q = 0; q < 4; q++) {
            float a = v[q] / ssum;
            al[tid + q * 32] = a;
            out[OFF_AL + b * 128 + tid + q * 32] = a;
        }
    }
    __syncthreads();

    for (int h = tid; h < 512; h += 256) {
        float acc = 0.f;
        for (int s = 0; s < 128; s++) acc += al[s] * stb[(size_t)s * 512 + h];
        ctx[h] = acc;
        out[OFF_CTX + b * 512 + h] = acc;
    }
    __syncthreads();

    if (tid < 10) {
        float acc = linb[tid];
        const float* wrow = linW + tid * 515;
        for (int h = 0; h < 512; h++) acc += ctx[h] * wrow[h];
        for (int d = 0; d < 3; d++) acc += demoip[b * 3 + d] * wrow[512 + d];
        o10[tid] = acc;
    }
    __syncthreads();
    if (tid < 10) {
        float m = -1e30f;
        for (int o = 0; o < 10; o++) m = fmaxf(m, o10[o]);
        float e = expf(o10[tid] - m), ssum = 0.f;
        for (int o = 0; o < 10; o++) ssum += expf(o10[o] - m);
        out[OFF_OUT + b * 10 + tid] = e / ssum;
    }
}

// ======== launch ============================================================
extern "C" void kernel_launch(void* const* d_in, const int* in_sizes, int n_in,
                              void* d_out, int out_size) {
    // batch_size may or may not be materialized as input[2] (size-1 scalar).
    int sh = (in_sizes[2] == 1) ? 1 : 0;

    const float* inp   = (const float*)d_in[0];
    const float* demo  = (const float*)d_in[1];
    const float* convw = (const float*)d_in[2 + sh];
    // conv_b at [3+sh] cancels in the softmax; unused.
    const float* embW  = (const float*)d_in[4 + sh];
    const float* Wi0   = (const float*)d_in[5 + sh];
    const float* Wh0   = (const float*)d_in[6 + sh];
    const float* bi0   = (const float*)d_in[7 + sh];
    const float* bh0   = (const float*)d_in[8 + sh];
    const float* Wi1   = (const float*)d_in[9 + sh];
    const float* Wh1   = (const float*)d_in[10 + sh];
    const float* bi1   = (const float*)d_in[11 + sh];
    const float* bh1   = (const float*)d_in[12 + sh];
    const float* attw  = (const float*)d_in[13 + sh];
    const float* linW  = (const float*)d_in[14 + sh];
    const float* linb  = (const float*)d_in[15 + sh];
    float* out = (float*)d_out;

    cudaFuncSetAttribute(gru_kernel, cudaFuncAttributeMaxDynamicSharedMemorySize, GRU_SMEM);

    void *pc, *pe, *p0, *ps0, *p1;
    cudaGetSymbolAddress(&pc, g_conv);
    cudaGetSymbolAddress(&pe, g_emb);
    cudaGetSymbolAddress(&p0, g_gi0);
    cudaGetSymbolAddress(&ps0, g_st0);
    cudaGetSymbolAddress(&p1, g_gi1);

    conv_pool_kernel<<<Bn * Sn, 256>>>(inp, convw, (float*)pc);

    dim3 ge(In / GBN, (Sn * Bn) / GBM);   // (8, 32)
    dim3 gg(G3 / GBN, (Sn * Bn) / GBM);   // (24, 32)
    gemm_tn<<<ge, 256>>>((const float*)pc, embW, nullptr, (float*)pe, In, 1);
    gemm_tn<<<gg, 256>>>((const float*)pe, Wi0, bi0, (float*)p0, G3, 0);

    gru_kernel<<<128, 512, GRU_SMEM>>>((const float*)p0, Wh0, bh0, (float*)ps0, 0);

    gemm_tn<<<gg, 256>>>((const float*)ps0, Wi1, bi1, (float*)p1, G3, 0);

    gru_kernel<<<128, 512, GRU_SMEM>>>((const float*)p1, Wh1, bh1, out + OFF_ST, 1);

    final_kernel<<<Bn, 256>>>(out + OFF_ST, attw, demo, linW, linb, out);
}

// round 9
// speedup vs baseline: 1.7864x; 1.0231x over previous
#include <cuda_runtime.h>
#include <cuda_bf16.h>
#include <cstdint>
#include <cstddef>
#include <math.h>

// Dims
#define Bn 32
#define Sn 128
#define Pn 32
#define In 512
#define Hn 512
#define G3 1536
#define On 10

// Output layout: out[32,10] | states[32,128,512] | context[32,512] | alpha[32,128]
#define OFF_OUT 0
#define OFF_ST  320
#define OFF_CTX 2097472
#define OFF_AL  2113856

// -------- scratch (__device__ globals; no allocations allowed) --------------
__device__ float g_conv[Sn*Bn*In];
__device__ float g_emb [Sn*Bn*In];
__device__ float g_gi0 [Sn*Bn*G3];
__device__ float g_st0 [Sn*Bn*Hn];
__device__ float g_gi1 [Sn*Bn*G3];
__device__ float g_hT2[2*Hn*Bn];     // double-buffered h, transposed [k][b]
// per-CTA step flags, each on its own 128B line. Two arrays (one per layer);
// each layer resets the OTHER layer's array (stream-ordered, race-free).
__device__ __align__(128) unsigned g_flagA[128*32];
__device__ __align__(128) unsigned g_flagB[128*32];

// -------- helpers -----------------------------------------------------------
__device__ __forceinline__ float wred(float v) {
    #pragma unroll
    for (int o = 16; o; o >>= 1) v += __shfl_xor_sync(0xffffffffu, v, o);
    return v;
}
__device__ __forceinline__ unsigned ld_acq(const unsigned* p) {
    unsigned v;
    asm volatile("ld.acquire.gpu.u32 %0,[%1];" : "=r"(v) : "l"(p) : "memory");
    return v;
}
__device__ __forceinline__ void st_rel(unsigned* p, unsigned v) {
    asm volatile("st.release.gpu.u32 [%0],%1;" :: "l"(p), "r"(v) : "memory");
}
__device__ __forceinline__ float ldcg(const float* p) {
    float v;
    asm volatile("ld.global.cg.f32 %0,[%1];" : "=f"(v) : "l"(p));
    return v;
}
#define FMA2(d,a,b) asm("fma.rn.f32x2 %0,%1,%2,%0;" : "+l"(d) : "l"(a), "l"(b))
#define BCAST2(d,f) asm("mov.b64 %0,{%1,%1};" : "=l"(d) : "f"(f))
#define PACK2(d,x,y) asm("mov.b64 %0,{%1,%2};" : "=l"(d) : "f"(x), "f"(y))
#define UNPK2(x,y,d) asm("mov.b64 {%0,%1},%2;" : "=f"(x), "=f"(y) : "l"(d))

// ======== K1: conv-attention pooling over P (conv_b cancels in softmax) =====
__global__ __launch_bounds__(256)
void conv_pool_kernel(const float* __restrict__ in, const float* __restrict__ conv_w,
                      float* __restrict__ conv_all) {
    __shared__ float cw[In];
    __shared__ float sc[Pn];
    __shared__ float at[Pn];
    const int tid = threadIdx.x;
    const int bx = blockIdx.x;          // b*S + s
    const int b = bx >> 7, s = bx & 127;
    const float* base = in + (size_t)bx * (Pn * In);

    if (tid < 128) ((float4*)cw)[tid] = ((const float4*)conv_w)[tid];
    __syncthreads();

    const int w = tid >> 5, lane = tid & 31;
    #pragma unroll
    for (int q = 0; q < 4; q++) {
        int p = w * 4 + q;
        const float4* row = (const float4*)(base + (size_t)p * In);
        const float4* cw4 = (const float4*)cw;
        float acc = 0.f;
        for (int kk = lane; kk < 128; kk += 32) {
            float4 x = row[kk], y = cw4[kk];
            acc += x.x*y.x + x.y*y.y + x.z*y.z + x.w*y.w;
        }
        acc = wred(acc);
        if (lane == 0) sc[p] = acc;
    }
    __syncthreads();

    if (tid < 32) {
        float v = sc[tid], m = v;
        #pragma unroll
        for (int o = 16; o; o >>= 1) m = fmaxf(m, __shfl_xor_sync(0xffffffffu, m, o));
        float e = expf(v - m);
        float ssum = wred(e);
        at[tid] = e / ssum;
    }
    __syncthreads();

    float* dst = conv_all + ((size_t)s * Bn + b) * In;   // row = s*32+b
    for (int i = tid; i < In; i += 256) {
        float acc = 0.f;
        #pragma unroll 8
        for (int p = 0; p < Pn; p++) acc += at[p] * base[(size_t)p * In + i];
        dst[i] = acc;
    }
}

// ======== GEMM  C[M,N] = act(A[M,512] @ W[N,512]^T + bias) ==================
// 128x128 tile, 256 threads, 8x8 thread tile (32 FMA2 per k per thread).
#define GBM 128
#define GBN 128
#define GBK 16
__global__ __launch_bounds__(256)
void gemm_tn(const float* __restrict__ A, const float* __restrict__ W,
             const float* __restrict__ bias, float* __restrict__ C,
             int N, int act) {
    __shared__ float As[GBK][GBM + 4];
    __shared__ float Ws[GBK][GBN + 4];
    const int tid = threadIdx.x;
    const int row0 = blockIdx.y * GBM;
    const int col0 = blockIdx.x * GBN;
    const int m0 = (tid >> 4) * 8;      // 0..120
    const int n0 = (tid & 15) * 8;      // 0..120
    unsigned long long acc[8][4];
    #pragma unroll
    for (int i = 0; i < 8; i++)
        #pragma unroll
        for (int j = 0; j < 4; j++) acc[i][j] = 0ULL;

    for (int k0 = 0; k0 < 512; k0 += GBK) {
        #pragma unroll
        for (int l = 0; l < 2; l++) {
            int idx = tid + l * 256;          // 0..511
            int m = idx & 127, kb = idx >> 7; // kb 0..3, 4 k each
            float4 v = *(const float4*)(A + (size_t)(row0 + m) * 512 + k0 + kb * 4);
            As[kb*4+0][m] = v.x; As[kb*4+1][m] = v.y;
            As[kb*4+2][m] = v.z; As[kb*4+3][m] = v.w;
        }
        #pragma unroll
        for (int l = 0; l < 2; l++) {
            int idx = tid + l * 256;
            int n = idx & 127, kb = idx >> 7;
            float4 v = *(const float4*)(W + (size_t)(col0 + n) * 512 + k0 + kb * 4);
            Ws[kb*4+0][n] = v.x; Ws[kb*4+1][n] = v.y;
            Ws[kb*4+2][n] = v.z; Ws[kb*4+3][n] = v.w;
        }
        __syncthreads();
        #pragma unroll
        for (int k = 0; k < GBK; k++) {
            float4 a0 = *(const float4*)&As[k][m0];
            float4 a1 = *(const float4*)&As[k][m0 + 4];
            float4 w0 = *(const float4*)&Ws[k][n0];
            float4 w1 = *(const float4*)&Ws[k][n0 + 4];
            unsigned long long wp0, wp1, wp2, wp3;
            PACK2(wp0, w0.x, w0.y);
            PACK2(wp1, w0.z, w0.w);
            PACK2(wp2, w1.x, w1.y);
            PACK2(wp3, w1.z, w1.w);
            float am[8] = {a0.x,a0.y,a0.z,a0.w,a1.x,a1.y,a1.z,a1.w};
            #pragma unroll
            for (int i = 0; i < 8; i++) {
                unsigned long long ai;
                BCAST2(ai, am[i]);
                FMA2(acc[i][0], ai, wp0);
                FMA2(acc[i][1], ai, wp1);
                FMA2(acc[i][2], ai, wp2);
                FMA2(acc[i][3], ai, wp3);
            }
        }
        __syncthreads();
    }
    float bv[8];
    #pragma unroll
    for (int j = 0; j < 8; j++) bv[j] = bias ? bias[col0 + n0 + j] : 0.f;
    #pragma unroll
    for (int i = 0; i < 8; i++) {
        float c[8];
        UNPK2(c[0], c[1], acc[i][0]);
        UNPK2(c[2], c[3], acc[i][1]);
        UNPK2(c[4], c[5], acc[i][2]);
        UNPK2(c[6], c[7], acc[i][3]);
        #pragma unroll
        for (int j = 0; j < 8; j++) {
            c[j] += bv[j];
            if (act == 1) c[j] = fminf(1.f, fmaxf(-1.f, c[j]));
        }
        float4 o0 = {c[0], c[1], c[2], c[3]};
        float4 o1 = {c[4], c[5], c[6], c[7]};
        *(float4*)(C + (size_t)(row0 + m0 + i) * N + col0 + n0) = o0;
        *(float4*)(C + (size_t)(row0 + m0 + i) * N + col0 + n0 + 4) = o1;
    }
}

// ======== GRU persistent recurrence (warp-autonomous 8-producer polling) ====
// grid=128 CTAs, 512 thr (16 warps). CTA c owns h-columns [4c,4c+4) (12 gate cols).
// Warp w: lane=b, k-slice = q*128 + (w&3)*32, q=((w>>2)+cta)&3. Columns
// k0..k0+31 are produced by exactly 8 CTAs (j>>2) -> each warp polls only ITS
// 8 producer flags (8 lines, 4 lanes/line, one parallel LDG + __all_sync).
// No named barriers. h read via ld.global.cg (coherent, no L1 pollution).
#define SM_WP   0
#define SM_RED  32768
#define SM_BH   (32768 + 26624)
#define GRU_SMEM (32768 + 26624 + 64)

__global__ __launch_bounds__(512)
void gru_kernel(const float* __restrict__ gi, const float* __restrict__ Whh,
                const float* __restrict__ bhh, float* __restrict__ st_out,
                int lay1) {
    extern __shared__ char sm[];
    float* wp  = (float*)(sm + SM_WP);    // [k][16] floats; cols c=0..11 (c=g*4+jl)
    float* red = (float*)(sm + SM_RED);   // [(w*32+b)*13 + c]
    float* bh  = (float*)(sm + SM_BH);    // [12]
    const int tid = threadIdx.x;
    const int cta = blockIdx.x;

    unsigned* flg = lay1 ? g_flagB : g_flagA;
    // reset the OTHER layer's flag (only touched by the previous launch)
    if (tid == 0) (lay1 ? g_flagA : g_flagB)[cta * 32] = 0;

    // weights: wp[k*16 + c] = Whh[(g*512 + cta*4 + jl)*512 + k], c = g*4+jl
    for (int i = tid; i < 6144; i += 512) {
        int c = i >> 9, k = i & 511;
        int g = c >> 2, jl = c & 3;
        wp[k * 16 + c] = Whh[(size_t)(g * 512 + cta * 4 + jl) * 512 + k];
    }
    if (tid < 12) bh[tid] = bhh[(tid >> 2) * 512 + cta * 4 + (tid & 3)];
    __syncthreads();

    const int lane = tid & 31, w = tid >> 5;
    const int q = ((w >> 2) + cta) & 3;          // chunk this warp consumes
    const int k0 = q * 128 + (w & 3) * 32;       // warp's 32-k slice
    const int pc0 = k0 >> 2;                     // first producer CTA of slice
    const unsigned* myflag = &flg[(pc0 + (lane & 7)) * 32];
    // gate-phase identity (tid < 128)
    const int bb = tid & 31, jl = (tid >> 5) & 3;
    const int jg = cta * 4 + jl;

    float giv0 = 0.f, giv1 = 0.f, giv2 = 0.f, ho = 0.f;
    if (tid < 128) {
        giv0 = __ldg(gi + (size_t)bb * G3 + jg);
        giv1 = __ldg(gi + (size_t)bb * G3 + 512 + jg);
        giv2 = __ldg(gi + (size_t)bb * G3 + 1024 + jg);
    }

    for (int s = 0; s < 128; s++) {
        if (s > 0) {
            // ---- warp-autonomous wait for THIS slice's 8 producers ----
            {
                unsigned tgt = (unsigned)s;
                while (!__all_sync(0xffffffffu, ld_acq(myflag) >= tgt)) { }
            }

            // ---- direct L2 read (cg): all 32 h loads in flight at once ----
            const float* hb = g_hT2 + ((s + 1) & 1) * (Hn * Bn) + (size_t)k0 * 32 + lane;
            float hr[32];
            #pragma unroll
            for (int i = 0; i < 32; i++) hr[i] = ldcg(hb + i * 32);

            unsigned long long acc[6];
            #pragma unroll
            for (int p = 0; p < 6; p++) acc[p] = 0ULL;
            #pragma unroll
            for (int i = 0; i < 32; i++) {
                unsigned long long h2;
                BCAST2(h2, hr[i]);
                const ulonglong2* wk = (const ulonglong2*)(wp + (k0 + i) * 16);
                ulonglong2 A = wk[0], Bv = wk[1], Cv = wk[2];
                FMA2(acc[0], h2, A.x);  FMA2(acc[1], h2, A.y);
                FMA2(acc[2], h2, Bv.x); FMA2(acc[3], h2, Bv.y);
                FMA2(acc[4], h2, Cv.x); FMA2(acc[5], h2, Cv.y);
            }
            float* rr = red + (w * 32 + lane) * 13;
            #pragma unroll
            for (int p = 0; p < 6; p++) {
                float x, y;
                UNPK2(x, y, acc[p]);
                rr[2 * p] = x; rr[2 * p + 1] = y;
            }
        }
        __syncthreads();

        // ---- gate math for the CTA's 4 columns ----
        float hn = 0.f;
        if (tid < 128) {
            float gh0 = 0.f, gh1 = 0.f, gh2 = 0.f;
            if (s > 0) {
                #pragma unroll
                for (int ww = 0; ww < 16; ww++) {
                    const float* rr = red + (ww * 32 + bb) * 13;
                    gh0 += rr[jl];
                    gh1 += rr[4 + jl];
                    gh2 += rr[8 + jl];
                }
            }
            float r = 1.f / (1.f + expf(-(giv0 + gh0 + bh[jl])));
            float z = 1.f / (1.f + expf(-(giv1 + gh1 + bh[4 + jl])));
            float nn = tanhf(giv2 + r * (gh2 + bh[8 + jl]));
            hn = (1.f - z) * nn + z * ho;
            ho = hn;
            g_hT2[(s & 1) * (Hn * Bn) + jg * 32 + bb] = hn;
        }
        __syncthreads();

        // ---- publish progress: ONE release store, no atomics ----
        if (tid == 0) st_rel(&flg[cta * 32], (unsigned)(s + 1));

        // ---- off-critical-path work: states write + next gi prefetch ----
        if (tid < 128) {
            size_t oidx = lay1 ? ((size_t)bb * 128 + s) * 512 + jg
                               : ((size_t)s * 32 + bb) * 512 + jg;
            st_out[oidx] = hn;
            if (s < 127) {
                size_t gib = ((size_t)(s + 1) * 32 + bb) * (size_t)G3;
                giv0 = __ldg(gi + gib + jg);
                giv1 = __ldg(gi + gib + 512 + jg);
                giv2 = __ldg(gi + gib + 1024 + jg);
            }
        }
    }
}

// ======== final: time-attention + linear + softmax ==========================
// states layout here: [b][s][h] (written directly by layer-1 GRU into d_out)
__global__ __launch_bounds__(256)
void final_kernel(const float* __restrict__ states, const float* __restrict__ attw,
                  const float* __restrict__ demoip, const float* __restrict__ linW,
                  const float* __restrict__ linb, float* __restrict__ out) {
    __shared__ float aw[512];
    __shared__ float lg[128];
    __shared__ float al[128];
    __shared__ float ctx[512];
    __shared__ float o10[10];
    const int tid = threadIdx.x, b = blockIdx.x;
    const int w = tid >> 5, lane = tid & 31;
    const float* stb = states + (size_t)b * 128 * 512;

    for (int h = tid; h < 512; h += 256) aw[h] = attw[h];
    __syncthreads();

    for (int s = w; s < 128; s += 8) {
        const float* row = stb + (size_t)s * 512;
        float acc = 0.f;
        for (int h = lane; h < 512; h += 32) acc += row[h] * aw[h];
        acc = wred(acc);
        if (lane == 0) lg[s] = acc;
    }
    __syncthreads();

    if (tid < 32) {
        float v[4]; float m = -1e30f;
        #pragma unroll
        for (int q = 0; q < 4; q++) { v[q] = lg[tid + q * 32]; m = fmaxf(m, v[q]); }
        #pragma unroll
        for (int o = 16; o; o >>= 1) m = fmaxf(m, __shfl_xor_sync(0xffffffffu, m, o));
        float ssum = 0.f;
        #pragma unroll
        for (int q = 0; q < 4; q++) { v[q] = expf(v[q] - m); ssum += v[q]; }
        ssum = wred(ssum);
        #pragma unroll
        for (int q = 0; q < 4; q++) {
            float a = v[q] / ssum;
            al[tid + q * 32] = a;
            out[OFF_AL + b * 128 + tid + q * 32] = a;
        }
    }
    __syncthreads();

    for (int h = tid; h < 512; h += 256) {
        float acc = 0.f;
        for (int s = 0; s < 128; s++) acc += al[s] * stb[(size_t)s * 512 + h];
        ctx[h] = acc;
        out[OFF_CTX + b * 512 + h] = acc;
    }
    __syncthreads();

    if (tid < 10) {
        float acc = linb[tid];
        const float* wrow = linW + tid * 515;
        for (int h = 0; h < 512; h++) acc += ctx[h] * wrow[h];
        for (int d = 0; d < 3; d++) acc += demoip[b * 3 + d] * wrow[512 + d];
        o10[tid] = acc;
    }
    __syncthreads();
    if (tid < 10) {
        float m = -1e30f;
        for (int o = 0; o < 10; o++) m = fmaxf(m, o10[o]);
        float e = expf(o10[tid] - m), ssum = 0.f;
        for (int o = 0; o < 10; o++) ssum += expf(o10[o] - m);
        out[OFF_OUT + b * 10 + tid] = e / ssum;
    }
}

// ======== launch ============================================================
extern "C" void kernel_launch(void* const* d_in, const int* in_sizes, int n_in,
                              void* d_out, int out_size) {
    // batch_size may or may not be materialized as input[2] (size-1 scalar).
    int sh = (in_sizes[2] == 1) ? 1 : 0;

    const float* inp   = (const float*)d_in[0];
    const float* demo  = (const float*)d_in[1];
    const float* convw = (const float*)d_in[2 + sh];
    // conv_b at [3+sh] cancels in the softmax; unused.
    const float* embW  = (const float*)d_in[4 + sh];
    const float* Wi0   = (const float*)d_in[5 + sh];
    const float* Wh0   = (const float*)d_in[6 + sh];
    const float* bi0   = (const float*)d_in[7 + sh];
    const float* bh0   = (const float*)d_in[8 + sh];
    const float* Wi1   = (const float*)d_in[9 + sh];
    const float* Wh1   = (const float*)d_in[10 + sh];
    const float* bi1   = (const float*)d_in[11 + sh];
    const float* bh1   = (const float*)d_in[12 + sh];
    const float* attw  = (const float*)d_in[13 + sh];
    const float* linW  = (const float*)d_in[14 + sh];
    const float* linb  = (const float*)d_in[15 + sh];
    float* out = (float*)d_out;

    cudaFuncSetAttribute(gru_kernel, cudaFuncAttributeMaxDynamicSharedMemorySize, GRU_SMEM);

    void *pc, *pe, *p0, *ps0, *p1;
    cudaGetSymbolAddress(&pc, g_conv);
    cudaGetSymbolAddress(&pe, g_emb);
    cudaGetSymbolAddress(&p0, g_gi0);
    cudaGetSymbolAddress(&ps0, g_st0);
    cudaGetSymbolAddress(&p1, g_gi1);

    conv_pool_kernel<<<Bn * Sn, 256>>>(inp, convw, (float*)pc);

    dim3 ge(In / GBN, (Sn * Bn) / GBM);   // (4, 32)
    dim3 gg(G3 / GBN, (Sn * Bn) / GBM);   // (12, 32)
    gemm_tn<<<ge, 256>>>((const float*)pc, embW, nullptr, (float*)pe, In, 1);
    gemm_tn<<<gg, 256>>>((const float*)pe, Wi0, bi0, (float*)p0, G3, 0);

    gru_kernel<<<128, 512, GRU_SMEM>>>((const float*)p0, Wh0, bh0, (float*)ps0, 0);

    gemm_tn<<<gg, 256>>>((const float*)ps0, Wi1, bi1, (float*)p1, G3, 0);

    gru_kernel<<<128, 512, GRU_SMEM>>>((const float*)p1, Wh1, bh1, out + OFF_ST, 1);

    final_kernel<<<Bn, 256>>>(out + OFF_ST, attw, demo, linW, linb, out);
}